// round 1
// baseline (speedup 1.0000x reference)
#include <cuda_runtime.h>
#include <math.h>

// Problem shape (fixed by the dataset)
#define B   2
#define T   2048
#define KD  256          // head dim
#define H   8
#define BH  (B*H)        // 16
#define NPROJ (KD*H)     // 2048
#define ROWS (B*T)       // 4096

// GEMM tiling
#define BM 64
#define BN 64
#define BK 16
#define PAD 8            // smem row stride BM+PAD = 72 floats (16B-aligned rows)

// Scratch (device globals: allocation-free per harness rules)
__device__ float g_Q[BH * T * KD];          // 32 MB, [bh, t, k], pre-scaled
__device__ float g_K[BH * T * KD];          // 32 MB
__device__ float g_V[BH * T * KD];          // 32 MB
__device__ float g_S[(size_t)BH * T * T];   // 256 MB, [bh, q, s]
__device__ float g_O[B * T * H * KD];       // 32 MB, [b, t, h, k] (== [4096, 2048])

// ---------------------------------------------------------------------------
// Kernel 1: projections. C[4096,2048] = x[4096,256] @ W[256,2048], scattered
// into [bh, t, k] layout. grid.z selects {Wq, Wk, Wv}. Q,K get scale 0.25.
// ---------------------------------------------------------------------------
__global__ void proj_kernel(const float* __restrict__ x,
                            const float* __restrict__ Wq,
                            const float* __restrict__ Wk,
                            const float* __restrict__ Wv) {
    __shared__ float As[BK][BM + PAD];
    __shared__ float Bs[BK][BN + PAD];

    const int which = blockIdx.z;
    const float* __restrict__ W = (which == 0) ? Wq : (which == 1) ? Wk : Wv;
    float* __restrict__ out = (which == 0) ? g_Q : (which == 1) ? g_K : g_V;
    const float scale = (which == 2) ? 1.0f : 0.25f;  // 256^-0.25 = 0.25

    const int m0 = blockIdx.y * BM;
    const int n0 = blockIdx.x * BN;
    const int tid = threadIdx.x;
    const int tx = tid & 15, ty = tid >> 4;

    float c[4][4] = {};

    for (int k0 = 0; k0 < KD; k0 += BK) {
        // A tile: x[m0+row][k0 .. k0+15], store transposed As[k][m]
        {
            int row = tid >> 2;
            int c4  = (tid & 3) * 4;
            float4 v = *(const float4*)&x[(m0 + row) * KD + k0 + c4];
            As[c4 + 0][row] = v.x; As[c4 + 1][row] = v.y;
            As[c4 + 2][row] = v.z; As[c4 + 3][row] = v.w;
        }
        // B tile: W[k0+row][n0 .. n0+63]
        {
            int row = tid >> 4;
            int c4  = (tid & 15) * 4;
            float4 v = *(const float4*)&W[(k0 + row) * NPROJ + n0 + c4];
            Bs[row][c4 + 0] = v.x; Bs[row][c4 + 1] = v.y;
            Bs[row][c4 + 2] = v.z; Bs[row][c4 + 3] = v.w;
        }
        __syncthreads();
        #pragma unroll
        for (int kk = 0; kk < BK; kk++) {
            float4 a4 = *(const float4*)&As[kk][ty * 4];
            float4 b4 = *(const float4*)&Bs[kk][tx * 4];
            float a[4] = {a4.x, a4.y, a4.z, a4.w};
            float bb[4] = {b4.x, b4.y, b4.z, b4.w};
            #pragma unroll
            for (int i = 0; i < 4; i++)
                #pragma unroll
                for (int j = 0; j < 4; j++)
                    c[i][j] += a[i] * bb[j];
        }
        __syncthreads();
    }

    // Scatter: row r -> (b, t); col cc -> (head, kk). Tile lies in one head.
    const int head = n0 >> 8;  // n0 is a multiple of 64; 64-tile within one 256-block
    #pragma unroll
    for (int i = 0; i < 4; i++) {
        int r  = m0 + ty * 4 + i;
        int bb_ = r / T, tt = r % T;
        float* orow = &out[(((bb_ * H + head) * T + tt) * KD) + ((n0 & 255) + tx * 4)];
        #pragma unroll
        for (int j = 0; j < 4; j++) orow[j] = c[i][j] * scale;
    }
}

// ---------------------------------------------------------------------------
// Kernel 2: S[bh] = Q[bh] @ K[bh]^T   (NT GEMM, M=N=2048, K=256)
// ---------------------------------------------------------------------------
__global__ void scores_kernel() {
    __shared__ float As[BK][BM + PAD];
    __shared__ float Bs[BK][BN + PAD];

    const int bh = blockIdx.z;
    const float* __restrict__ Q  = g_Q + bh * T * KD;
    const float* __restrict__ Kp = g_K + bh * T * KD;
    float* __restrict__ S = g_S + (size_t)bh * T * T;

    const int m0 = blockIdx.y * BM;
    const int n0 = blockIdx.x * BN;
    const int tid = threadIdx.x;
    const int tx = tid & 15, ty = tid >> 4;

    float c[4][4] = {};

    for (int k0 = 0; k0 < KD; k0 += BK) {
        {
            int row = tid >> 2;
            int c4  = (tid & 3) * 4;
            float4 v = *(const float4*)&Q[(m0 + row) * KD + k0 + c4];
            As[c4 + 0][row] = v.x; As[c4 + 1][row] = v.y;
            As[c4 + 2][row] = v.z; As[c4 + 3][row] = v.w;
        }
        {
            int row = tid >> 2;
            int c4  = (tid & 3) * 4;
            float4 v = *(const float4*)&Kp[(n0 + row) * KD + k0 + c4];
            Bs[c4 + 0][row] = v.x; Bs[c4 + 1][row] = v.y;
            Bs[c4 + 2][row] = v.z; Bs[c4 + 3][row] = v.w;
        }
        __syncthreads();
        #pragma unroll
        for (int kk = 0; kk < BK; kk++) {
            float4 a4 = *(const float4*)&As[kk][ty * 4];
            float4 b4 = *(const float4*)&Bs[kk][tx * 4];
            float a[4] = {a4.x, a4.y, a4.z, a4.w};
            float bb[4] = {b4.x, b4.y, b4.z, b4.w};
            #pragma unroll
            for (int i = 0; i < 4; i++)
                #pragma unroll
                for (int j = 0; j < 4; j++)
                    c[i][j] += a[i] * bb[j];
        }
        __syncthreads();
    }

    #pragma unroll
    for (int i = 0; i < 4; i++) {
        float* srow = &S[(size_t)(m0 + ty * 4 + i) * T + n0 + tx * 4];
        #pragma unroll
        for (int j = 0; j < 4; j++) srow[j] = c[i][j];
    }
}

// ---------------------------------------------------------------------------
// Kernel 3: row softmax over S (in place). One block per row, 256 threads.
// ---------------------------------------------------------------------------
__device__ __forceinline__ float warpMax(float v) {
    #pragma unroll
    for (int o = 16; o > 0; o >>= 1) v = fmaxf(v, __shfl_xor_sync(0xffffffffu, v, o));
    return v;
}
__device__ __forceinline__ float warpSum(float v) {
    #pragma unroll
    for (int o = 16; o > 0; o >>= 1) v += __shfl_xor_sync(0xffffffffu, v, o);
    return v;
}

__global__ void softmax_kernel() {
    const int row = blockIdx.x;
    const int bh  = blockIdx.y;
    float* __restrict__ S = g_S + ((size_t)bh * T + row) * T;
    const int tid = threadIdx.x;
    const int lane = tid & 31, wid = tid >> 5;
    __shared__ float red[8];

    float vals[8];
    float m = -INFINITY;
    #pragma unroll
    for (int i = 0; i < 8; i++) {
        vals[i] = S[tid + i * 256];
        m = fmaxf(m, vals[i]);
    }
    m = warpMax(m);
    if (lane == 0) red[wid] = m;
    __syncthreads();
    float bm = red[0];
    #pragma unroll
    for (int w = 1; w < 8; w++) bm = fmaxf(bm, red[w]);

    float s = 0.f;
    #pragma unroll
    for (int i = 0; i < 8; i++) {
        vals[i] = expf(vals[i] - bm);
        s += vals[i];
    }
    s = warpSum(s);
    __syncthreads();
    if (lane == 0) red[wid] = s;
    __syncthreads();
    float bs = 0.f;
    #pragma unroll
    for (int w = 0; w < 8; w++) bs += red[w];
    float inv = 1.0f / bs;

    #pragma unroll
    for (int i = 0; i < 8; i++) S[tid + i * 256] = vals[i] * inv;
}

// ---------------------------------------------------------------------------
// Kernel 4: O[bh] = S[bh] @ V[bh]   (NN GEMM, M=2048, N=256, K=2048),
// written into [b, t, h, k] layout (== [4096, 2048] row-major).
// ---------------------------------------------------------------------------
__global__ void av_kernel() {
    __shared__ float As[BK][BM + PAD];
    __shared__ float Bs[BK][BN + PAD];

    const int bh = blockIdx.z;
    const int bb_ = bh >> 3, head = bh & 7;
    const float* __restrict__ S = g_S + (size_t)bh * T * T;
    const float* __restrict__ V = g_V + bh * T * KD;

    const int m0 = blockIdx.y * BM;   // q
    const int n0 = blockIdx.x * BN;   // k within head (0..255)
    const int tid = threadIdx.x;
    const int tx = tid & 15, ty = tid >> 4;

    float c[4][4] = {};

    for (int k0 = 0; k0 < T; k0 += BK) {
        {
            int row = tid >> 2;
            int c4  = (tid & 3) * 4;
            float4 v = *(const float4*)&S[(size_t)(m0 + row) * T + k0 + c4];
            As[c4 + 0][row] = v.x; As[c4 + 1][row] = v.y;
            As[c4 + 2][row] = v.z; As[c4 + 3][row] = v.w;
        }
        {
            int row = tid >> 4;
            int c4  = (tid & 15) * 4;
            float4 v = *(const float4*)&V[(k0 + row) * KD + n0 + c4];
            Bs[row][c4 + 0] = v.x; Bs[row][c4 + 1] = v.y;
            Bs[row][c4 + 2] = v.z; Bs[row][c4 + 3] = v.w;
        }
        __syncthreads();
        #pragma unroll
        for (int kk = 0; kk < BK; kk++) {
            float4 a4 = *(const float4*)&As[kk][ty * 4];
            float4 b4 = *(const float4*)&Bs[kk][tx * 4];
            float a[4] = {a4.x, a4.y, a4.z, a4.w};
            float bb[4] = {b4.x, b4.y, b4.z, b4.w};
            #pragma unroll
            for (int i = 0; i < 4; i++)
                #pragma unroll
                for (int j = 0; j < 4; j++)
                    c[i][j] += a[i] * bb[j];
        }
        __syncthreads();
    }

    #pragma unroll
    for (int i = 0; i < 4; i++) {
        int q = m0 + ty * 4 + i;
        float* orow = &g_O[((bb_ * T + q) * H + head) * KD + n0 + tx * 4];
        #pragma unroll
        for (int j = 0; j < 4; j++) orow[j] = c[i][j];
    }
}

// ---------------------------------------------------------------------------
// Kernel 5: out = g_O[4096,2048] @ Wu[2048,256] + bu
// ---------------------------------------------------------------------------
__global__ void final_kernel(const float* __restrict__ Wu,
                             const float* __restrict__ bu,
                             float* __restrict__ out) {
    __shared__ float As[BK][BM + PAD];
    __shared__ float Bs[BK][BN + PAD];

    const int m0 = blockIdx.y * BM;
    const int n0 = blockIdx.x * BN;
    const int tid = threadIdx.x;
    const int tx = tid & 15, ty = tid >> 4;

    float c[4][4] = {};

    for (int k0 = 0; k0 < NPROJ; k0 += BK) {
        {
            int row = tid >> 2;
            int c4  = (tid & 3) * 4;
            float4 v = *(const float4*)&g_O[(m0 + row) * NPROJ + k0 + c4];
            As[c4 + 0][row] = v.x; As[c4 + 1][row] = v.y;
            As[c4 + 2][row] = v.z; As[c4 + 3][row] = v.w;
        }
        {
            int row = tid >> 4;
            int c4  = (tid & 15) * 4;
            float4 v = *(const float4*)&Wu[(k0 + row) * KD + n0 + c4];
            Bs[row][c4 + 0] = v.x; Bs[row][c4 + 1] = v.y;
            Bs[row][c4 + 2] = v.z; Bs[row][c4 + 3] = v.w;
        }
        __syncthreads();
        #pragma unroll
        for (int kk = 0; kk < BK; kk++) {
            float4 a4 = *(const float4*)&As[kk][ty * 4];
            float4 b4 = *(const float4*)&Bs[kk][tx * 4];
            float a[4] = {a4.x, a4.y, a4.z, a4.w};
            float bb[4] = {b4.x, b4.y, b4.z, b4.w};
            #pragma unroll
            for (int i = 0; i < 4; i++)
                #pragma unroll
                for (int j = 0; j < 4; j++)
                    c[i][j] += a[i] * bb[j];
        }
        __syncthreads();
    }

    #pragma unroll
    for (int i = 0; i < 4; i++) {
        float* orow = &out[(m0 + ty * 4 + i) * KD + n0 + tx * 4];
        #pragma unroll
        for (int j = 0; j < 4; j++) orow[j] = c[i][j] + bu[n0 + tx * 4 + j];
    }
}

// ---------------------------------------------------------------------------
extern "C" void kernel_launch(void* const* d_in, const int* in_sizes, int n_in,
                              void* d_out, int out_size) {
    const float* x  = (const float*)d_in[0];
    const float* Wq = (const float*)d_in[1];
    const float* Wk = (const float*)d_in[2];
    const float* Wv = (const float*)d_in[3];
    const float* Wu = (const float*)d_in[4];
    const float* bu = (const float*)d_in[5];
    float* out = (float*)d_out;

    // 1) Q,K,V projections (3 GEMMs via grid.z)
    {
        dim3 grid(NPROJ / BN, ROWS / BM, 3);
        proj_kernel<<<grid, 256>>>(x, Wq, Wk, Wv);
    }
    // 2) S = Q K^T per (b,h)
    {
        dim3 grid(T / BN, T / BM, BH);
        scores_kernel<<<grid, 256>>>();
    }
    // 3) softmax rows
    {
        dim3 grid(T, BH);
        softmax_kernel<<<grid, 256>>>();
    }
    // 4) O = S V per (b,h), scattered into [b,t,h*k]
    {
        dim3 grid(KD / BN, T / BM, BH);
        av_kernel<<<grid, 256>>>();
    }
    // 5) out = O @ Wu + bu
    {
        dim3 grid(KD / BN, ROWS / BM);
        final_kernel<<<grid, 256>>>(Wu, bu, out);
    }
}

// round 3
// speedup vs baseline: 3.2329x; 3.2329x over previous
#include <cuda_runtime.h>
#include <math.h>
#include <stdint.h>

// Problem shape (fixed)
#define B   2
#define T   2048
#define KD  256
#define H   8
#define BH  (B*H)        // 16
#define NPROJ (KD*H)     // 2048
#define ROWS (B*T)       // 4096

// ---------------------------------------------------------------------------
// Scratch (device globals — allocation-free per harness rules)
// ---------------------------------------------------------------------------
__device__ float g_Q [BH * T * KD];           // [bh][t][kd], pre-scaled by 0.25
__device__ float g_K [BH * T * KD];           // [bh][t][kd], pre-scaled by 0.25
__device__ float g_Vt[BH * KD * T];           // [bh][kd][t]  (V transposed)
__device__ float g_S [(size_t)BH * T * T];    // [bh][q][s]  256 MB
__device__ float g_O [ROWS * NPROJ];          // [b*t][h*kd]
__device__ float g_Wt [3 * NPROJ * KD];       // Wq^T,Wk^T,Wv^T : [n][k]
__device__ float g_Wut[KD * NPROJ];           // Wu^T : [n=256][k=2048]

// ---------------------------------------------------------------------------
// Tiling: CTA 128x128, 8 warps as 2(m) x 4(n); warp tile 64x32; BK=32.
// Smem: row-major [row][k] with stride 36 floats (conflict-free for both
// STS.128 (bank phase r+kq mod 8) and fragment LDS (bank 4g+tig, unique)).
// ---------------------------------------------------------------------------
#define BK    32
#define LDSW  36                          // smem row stride in floats
#define BUF_FLOATS (128 * LDSW)           // 4608 floats = 18432 B
#define SM_TOTAL (4 * BUF_FLOATS * 4)     // A0,A1,B0,B1 = 73728 B

#define MODE_PROJ   0
#define MODE_SCORES 1
#define MODE_AV     2
#define MODE_FINAL  3

__device__ __forceinline__ float tf32r(float x) {   // round-to-nearest tf32
    float r;
    asm("cvt.rna.tf32.f32 %0, %1;" : "=f"(r) : "f"(x));
    return r;
}

__device__ __forceinline__ void mma8(float c[4], const uint32_t a[4],
                                     const uint32_t b[2]) {
    asm volatile(
        "mma.sync.aligned.m16n8k8.row.col.f32.tf32.tf32.f32 "
        "{%0,%1,%2,%3}, {%4,%5,%6,%7}, {%8,%9}, {%0,%1,%2,%3};"
        : "+f"(c[0]), "+f"(c[1]), "+f"(c[2]), "+f"(c[3])
        : "r"(a[0]), "r"(a[1]), "r"(a[2]), "r"(a[3]), "r"(b[0]), "r"(b[1]));
}

__global__ void __launch_bounds__(256, 1)
gemm_mma(int mode, const float* __restrict__ pA,
         const float* __restrict__ pBias, float* __restrict__ pC) {
    extern __shared__ float smem[];
    float* sA[2] = { smem,                  smem + BUF_FLOATS };
    float* sB[2] = { smem + 2 * BUF_FLOATS, smem + 3 * BUF_FLOATS };

    const int tid  = threadIdx.x;
    const int lane = tid & 31, wid = tid >> 5;
    const int g    = lane >> 2, tig = lane & 3;
    const int wm   = (wid & 1) * 64;          // warp m-offset in CTA tile
    const int wn   = (wid >> 1) * 32;         // warp n-offset
    const int m0   = blockIdx.y * 128, n0 = blockIdx.x * 128;
    const int z    = blockIdx.z;

    // per-mode operands: A row-major [M][K]-chunked (lda), B K-major [N][K] (ldb)
    const float *A, *Bm;
    int lda, ldb, nch;
    if (mode == MODE_PROJ) {
        A = pA; lda = KD;
        Bm = g_Wt + (size_t)z * NPROJ * KD; ldb = KD; nch = KD / BK;
    } else if (mode == MODE_SCORES) {
        A  = g_Q + (size_t)z * T * KD; lda = KD;
        Bm = g_K + (size_t)z * T * KD; ldb = KD; nch = KD / BK;
    } else if (mode == MODE_AV) {
        A  = g_S  + (size_t)z * T * T;  lda = T;
        Bm = g_Vt + (size_t)z * KD * T; ldb = T; nch = T / BK;
    } else {
        A  = g_O;   lda = NPROJ;
        Bm = g_Wut; ldb = NPROJ;        nch = NPROJ / BK;
    }

    // per-thread load coordinates (4 float4 each for A and B per chunk)
    const int lr[4] = { (tid + 0)   >> 3, (tid + 256) >> 3,
                        (tid + 512) >> 3, (tid + 768) >> 3 };
    const int lk = (tid & 7) * 4;

    float acc[4][4][4];
    #pragma unroll
    for (int mi = 0; mi < 4; mi++)
        #pragma unroll
        for (int ni = 0; ni < 4; ni++)
            #pragma unroll
            for (int r = 0; r < 4; r++) acc[mi][ni][r] = 0.f;

    float4 ra[4], rb[4];
    // prologue loads (chunk 0)
    #pragma unroll
    for (int i = 0; i < 4; i++) {
        ra[i] = *(const float4*)&A [(size_t)(m0 + lr[i]) * lda + lk];
        rb[i] = *(const float4*)&Bm[(size_t)(n0 + lr[i]) * ldb + lk];
    }

    for (int c = 0; c < nch; c++) {
        const int st = c & 1;
        float* __restrict__ a_s = sA[st];
        float* __restrict__ b_s = sB[st];
        // store current chunk (tf32-rounded)
        #pragma unroll
        for (int i = 0; i < 4; i++) {
            float4 wa = { tf32r(ra[i].x), tf32r(ra[i].y), tf32r(ra[i].z), tf32r(ra[i].w) };
            float4 wb = { tf32r(rb[i].x), tf32r(rb[i].y), tf32r(rb[i].z), tf32r(rb[i].w) };
            *(float4*)&a_s[lr[i] * LDSW + lk] = wa;
            *(float4*)&b_s[lr[i] * LDSW + lk] = wb;
        }
        __syncthreads();
        // issue next chunk's global loads early (overlap with MMA)
        if (c + 1 < nch) {
            const int k0 = (c + 1) * BK + lk;
            #pragma unroll
            for (int i = 0; i < 4; i++) {
                ra[i] = *(const float4*)&A [(size_t)(m0 + lr[i]) * lda + k0];
                rb[i] = *(const float4*)&Bm[(size_t)(n0 + lr[i]) * ldb + k0];
            }
        }
        // MMA over this chunk: 4 k-steps of 8
        const uint32_t* au = (const uint32_t*)a_s;
        const uint32_t* bu = (const uint32_t*)b_s;
        #pragma unroll
        for (int ks = 0; ks < 4; ks++) {
            const int k = ks * 8;
            uint32_t af[4][4], bf[4][2];
            #pragma unroll
            for (int mi = 0; mi < 4; mi++) {
                const int row = wm + mi * 16 + g;
                af[mi][0] = au[(row)     * LDSW + k + tig];
                af[mi][1] = au[(row + 8) * LDSW + k + tig];
                af[mi][2] = au[(row)     * LDSW + k + tig + 4];
                af[mi][3] = au[(row + 8) * LDSW + k + tig + 4];
            }
            #pragma unroll
            for (int ni = 0; ni < 4; ni++) {
                const int col = wn + ni * 8 + g;
                bf[ni][0] = bu[col * LDSW + k + tig];
                bf[ni][1] = bu[col * LDSW + k + tig + 4];
            }
            #pragma unroll
            for (int mi = 0; mi < 4; mi++)
                #pragma unroll
                for (int ni = 0; ni < 4; ni++)
                    mma8(acc[mi][ni], af[mi], bf[ni]);
        }
        __syncthreads();
    }

    // ------------------- epilogue (fragment -> gmem, per mode) -------------
    #pragma unroll
    for (int mi = 0; mi < 4; mi++) {
        const int r0 = m0 + wm + mi * 16 + g;     // global row
        const int r1 = r0 + 8;
        #pragma unroll
        for (int ni = 0; ni < 4; ni++) {
            const int cc = n0 + wn + ni * 8 + tig * 2;  // global col (even)
            const float* v = acc[mi][ni];
            if (mode == MODE_SCORES) {
                float* Cb = g_S + (size_t)z * T * T;
                *(float2*)&Cb[(size_t)r0 * T + cc] = make_float2(v[0], v[1]);
                *(float2*)&Cb[(size_t)r1 * T + cc] = make_float2(v[2], v[3]);
            } else if (mode == MODE_PROJ) {
                const int head = n0 >> 8;             // 128-tile inside one head
                const int colh = (n0 & 255) + (cc - n0);
                const int b0_ = r0 >> 11, t0_ = r0 & 2047;
                const int b1_ = r1 >> 11, t1_ = r1 & 2047;
                if (z < 2) {
                    float* Cb = (z == 0) ? g_Q : g_K;
                    float* p0 = &Cb[(((size_t)(b0_ * H + head)) * T + t0_) * KD + colh];
                    float* p1 = &Cb[(((size_t)(b1_ * H + head)) * T + t1_) * KD + colh];
                    *(float2*)p0 = make_float2(v[0] * 0.25f, v[1] * 0.25f);
                    *(float2*)p1 = make_float2(v[2] * 0.25f, v[3] * 0.25f);
                } else {
                    // V transposed: g_Vt[(bh*KD + colh)][t]
                    float* base0 = &g_Vt[(((size_t)(b0_ * H + head)) * KD + colh) * T];
                    float* base1 = &g_Vt[(((size_t)(b1_ * H + head)) * KD + colh) * T];
                    base0[t0_] = v[0]; base0[T + t0_] = v[1];
                    base1[t1_] = v[2]; base1[T + t1_] = v[3];
                }
            } else if (mode == MODE_AV) {
                const int b_ = z >> 3, head = z & 7;
                float* p0 = &g_O[((size_t)(b_ * T + r0)) * NPROJ + head * KD + cc];
                float* p1 = &g_O[((size_t)(b_ * T + r1)) * NPROJ + head * KD + cc];
                *(float2*)p0 = make_float2(v[0], v[1]);
                *(float2*)p1 = make_float2(v[2], v[3]);
            } else {
                const float b0v = pBias[cc], b1v = pBias[cc + 1];
                *(float2*)&pC[(size_t)r0 * KD + cc] = make_float2(v[0] + b0v, v[1] + b1v);
                *(float2*)&pC[(size_t)r1 * KD + cc] = make_float2(v[2] + b0v, v[3] + b1v);
            }
        }
    }
}

// ---------------------------------------------------------------------------
// Weight transposes (one-shot, cheap)
// ---------------------------------------------------------------------------
__global__ void transpose_w(const float* __restrict__ in, int which) {
    // in: [KD=256][NPROJ=2048] -> g_Wt[which]: [2048][256]
    __shared__ float t[32][33];
    float* out = g_Wt + (size_t)which * NPROJ * KD;
    int c0 = blockIdx.x * 32, r0 = blockIdx.y * 32;
    int x = threadIdx.x, y = threadIdx.y;
    #pragma unroll
    for (int i = 0; i < 32; i += 8)
        t[y + i][x] = in[(size_t)(r0 + y + i) * NPROJ + c0 + x];
    __syncthreads();
    #pragma unroll
    for (int i = 0; i < 32; i += 8)
        out[(size_t)(c0 + y + i) * KD + r0 + x] = t[x][y + i];
}
__global__ void transpose_wu(const float* __restrict__ in) {
    // in: [NPROJ=2048][KD=256] -> g_Wut: [256][2048]
    __shared__ float t[32][33];
    int c0 = blockIdx.x * 32, r0 = blockIdx.y * 32;
    int x = threadIdx.x, y = threadIdx.y;
    #pragma unroll
    for (int i = 0; i < 32; i += 8)
        t[y + i][x] = in[(size_t)(r0 + y + i) * KD + c0 + x];
    __syncthreads();
    #pragma unroll
    for (int i = 0; i < 32; i += 8)
        g_Wut[(size_t)(c0 + y + i) * NPROJ + r0 + x] = t[x][y + i];
}

// ---------------------------------------------------------------------------
// Row softmax over S, in place (fp32)
// ---------------------------------------------------------------------------
__device__ __forceinline__ float warpMax(float v) {
    #pragma unroll
    for (int o = 16; o > 0; o >>= 1) v = fmaxf(v, __shfl_xor_sync(0xffffffffu, v, o));
    return v;
}
__device__ __forceinline__ float warpSum(float v) {
    #pragma unroll
    for (int o = 16; o > 0; o >>= 1) v += __shfl_xor_sync(0xffffffffu, v, o);
    return v;
}
__global__ void softmax_kernel() {
    const int row = blockIdx.x, bh = blockIdx.y;
    float* __restrict__ S = g_S + ((size_t)bh * T + row) * T;
    const int tid = threadIdx.x, lane = tid & 31, wid = tid >> 5;
    __shared__ float red[8];

    float vals[8];
    float m = -INFINITY;
    #pragma unroll
    for (int i = 0; i < 8; i++) { vals[i] = S[tid + i * 256]; m = fmaxf(m, vals[i]); }
    m = warpMax(m);
    if (lane == 0) red[wid] = m;
    __syncthreads();
    float bm = red[0];
    #pragma unroll
    for (int w = 1; w < 8; w++) bm = fmaxf(bm, red[w]);

    float s = 0.f;
    #pragma unroll
    for (int i = 0; i < 8; i++) { vals[i] = expf(vals[i] - bm); s += vals[i]; }
    s = warpSum(s);
    __syncthreads();
    if (lane == 0) red[wid] = s;
    __syncthreads();
    float bs = 0.f;
    #pragma unroll
    for (int w = 0; w < 8; w++) bs += red[w];
    const float inv = 1.0f / bs;
    #pragma unroll
    for (int i = 0; i < 8; i++) S[tid + i * 256] = vals[i] * inv;
}

// ---------------------------------------------------------------------------
extern "C" void kernel_launch(void* const* d_in, const int* in_sizes, int n_in,
                              void* d_out, int out_size) {
    const float* x  = (const float*)d_in[0];
    const float* Wq = (const float*)d_in[1];
    const float* Wk = (const float*)d_in[2];
    const float* Wv = (const float*)d_in[3];
    const float* Wu = (const float*)d_in[4];
    const float* bu = (const float*)d_in[5];
    float* out = (float*)d_out;

    cudaFuncSetAttribute(gemm_mma,
                         cudaFuncAttributeMaxDynamicSharedMemorySize, SM_TOTAL);

    // 0) transpose weights to K-major B operands
    transpose_w <<<dim3(NPROJ / 32, KD / 32), dim3(32, 8)>>>(Wq, 0);
    transpose_w <<<dim3(NPROJ / 32, KD / 32), dim3(32, 8)>>>(Wk, 1);
    transpose_w <<<dim3(NPROJ / 32, KD / 32), dim3(32, 8)>>>(Wv, 2);
    transpose_wu<<<dim3(KD / 32, NPROJ / 32), dim3(32, 8)>>>(Wu);

    // 1) projections: [4096,256] @ [256,2048], z = {q,k,v}; V written transposed
    gemm_mma<<<dim3(NPROJ / 128, ROWS / 128, 3), 256, SM_TOTAL>>>(
        MODE_PROJ, x, nullptr, nullptr);

    // 2) S = Q K^T per (b,h)
    gemm_mma<<<dim3(T / 128, T / 128, BH), 256, SM_TOTAL>>>(
        MODE_SCORES, nullptr, nullptr, nullptr);

    // 3) softmax rows
    softmax_kernel<<<dim3(T, BH), 256>>>();

    // 4) O = P V per (b,h) -> [b,t,h*kd]
    gemm_mma<<<dim3(KD / 128, T / 128, BH), 256, SM_TOTAL>>>(
        MODE_AV, nullptr, nullptr, nullptr);

    // 5) out = O @ Wu + bu
    gemm_mma<<<dim3(KD / 128, ROWS / 128, 1), 256, SM_TOTAL>>>(
        MODE_FINAL, nullptr, bu, out);
}

// round 4
// speedup vs baseline: 4.6400x; 1.4352x over previous
#include <cuda_runtime.h>
#include <cuda_fp16.h>
#include <math.h>
#include <stdint.h>

// Problem shape (fixed)
#define B   2
#define T   2048
#define KD  256
#define H   8
#define BH  (B*H)        // 16
#define NPROJ (KD*H)     // 2048
#define ROWS (B*T)       // 4096

// ---------------------------------------------------------------------------
// Scratch (device globals — allocation-free per harness rules)
// ---------------------------------------------------------------------------
__device__ float g_Q [BH * T * KD];           // [bh][t][kd], pre-scaled by 0.25
__device__ float g_K [BH * T * KD];           // [bh][t][kd], pre-scaled by 0.25
__device__ float g_Vt[BH * KD * T];           // [bh][kd][t]  (V transposed)
__device__ float g_S [(size_t)BH * T * T];    // [bh][q][s]  256 MB
__device__ float g_O [ROWS * NPROJ];          // [b*t][h*kd]
__device__ float g_Wt [3 * NPROJ * KD];       // Wq^T,Wk^T,Wv^T : [n][k]
__device__ float g_Wut[KD * NPROJ];           // Wu^T : [n=256][k=2048]

// ---------------------------------------------------------------------------
// Tiling: CTA 128x128, 8 warps as 2(m) x 4(n); warp tile 64x32; BK=32.
// Smem: half-precision, [row][k] stride 36 halves (72B = 18 banks):
// fragment u32 loads hit banks (18g + tig) mod 32, all distinct.
// ---------------------------------------------------------------------------
#define BK    32
#define LDSW  36                          // smem row stride in HALVES
#define BUF_HALFS (128 * LDSW)            // 4608 halves = 9216 B per buffer
#define SM_TOTAL (4 * BUF_HALFS * 2)      // A0,A1,B0,B1 = 36864 B

#define MODE_PROJ   0
#define MODE_SCORES 1
#define MODE_AV     2
#define MODE_FINAL  3

__device__ __forceinline__ uint32_t packh2(float x, float y) {
    __half2 h = __floats2half2_rn(x, y);
    return *(uint32_t*)&h;
}

__device__ __forceinline__ void mma16(float c[4], const uint32_t a[4],
                                      const uint32_t b[2]) {
    asm volatile(
        "mma.sync.aligned.m16n8k16.row.col.f32.f16.f16.f32 "
        "{%0,%1,%2,%3}, {%4,%5,%6,%7}, {%8,%9}, {%0,%1,%2,%3};"
        : "+f"(c[0]), "+f"(c[1]), "+f"(c[2]), "+f"(c[3])
        : "r"(a[0]), "r"(a[1]), "r"(a[2]), "r"(a[3]), "r"(b[0]), "r"(b[1]));
}

__global__ void __launch_bounds__(256, 2)
gemm_mma(int mode, const float* __restrict__ pA,
         const float* __restrict__ pBias, float* __restrict__ pC) {
    extern __shared__ __half smem[];
    __half* sA[2] = { smem,                 smem + BUF_HALFS };
    __half* sB[2] = { smem + 2 * BUF_HALFS, smem + 3 * BUF_HALFS };

    const int tid  = threadIdx.x;
    const int lane = tid & 31, wid = tid >> 5;
    const int g    = lane >> 2, tig = lane & 3;
    const int wm   = (wid & 1) * 64;          // warp m-offset in CTA tile
    const int wn   = (wid >> 1) * 32;         // warp n-offset
    const int m0   = blockIdx.y * 128, n0 = blockIdx.x * 128;
    const int z    = blockIdx.z;

    // per-mode operands: A row-major [M][K] (lda), B K-major [N][K] (ldb)
    const float *A, *Bm;
    int lda, ldb, nch;
    if (mode == MODE_PROJ) {
        A = pA; lda = KD;
        Bm = g_Wt + (size_t)z * NPROJ * KD; ldb = KD; nch = KD / BK;
    } else if (mode == MODE_SCORES) {
        A  = g_Q + (size_t)z * T * KD; lda = KD;
        Bm = g_K + (size_t)z * T * KD; ldb = KD; nch = KD / BK;
    } else if (mode == MODE_AV) {
        A  = g_S  + (size_t)z * T * T;  lda = T;
        Bm = g_Vt + (size_t)z * KD * T; ldb = T; nch = T / BK;
    } else {
        A  = g_O;   lda = NPROJ;
        Bm = g_Wut; ldb = NPROJ;        nch = NPROJ / BK;
    }

    // per-thread load coordinates (4 float4 each for A and B per chunk)
    const int lr[4] = { (tid + 0)   >> 3, (tid + 256) >> 3,
                        (tid + 512) >> 3, (tid + 768) >> 3 };
    const int lk = (tid & 7) * 4;             // in elements (floats / halves)

    float acc[4][4][4];
    #pragma unroll
    for (int mi = 0; mi < 4; mi++)
        #pragma unroll
        for (int ni = 0; ni < 4; ni++)
            #pragma unroll
            for (int r = 0; r < 4; r++) acc[mi][ni][r] = 0.f;

    float4 ra[4], rb[4];
    // prologue loads (chunk 0)
    #pragma unroll
    for (int i = 0; i < 4; i++) {
        ra[i] = *(const float4*)&A [(size_t)(m0 + lr[i]) * lda + lk];
        rb[i] = *(const float4*)&Bm[(size_t)(n0 + lr[i]) * ldb + lk];
    }

    for (int c = 0; c < nch; c++) {
        const int st = c & 1;
        __half* __restrict__ a_s = sA[st];
        __half* __restrict__ b_s = sB[st];
        // store current chunk as fp16 (round-to-nearest)
        #pragma unroll
        for (int i = 0; i < 4; i++) {
            uint2 wa = { packh2(ra[i].x, ra[i].y), packh2(ra[i].z, ra[i].w) };
            uint2 wb = { packh2(rb[i].x, rb[i].y), packh2(rb[i].z, rb[i].w) };
            *(uint2*)&a_s[lr[i] * LDSW + lk] = wa;
            *(uint2*)&b_s[lr[i] * LDSW + lk] = wb;
        }
        __syncthreads();
        // issue next chunk's global loads early (overlap with MMA)
        if (c + 1 < nch) {
            const int k0 = (c + 1) * BK + lk;
            #pragma unroll
            for (int i = 0; i < 4; i++) {
                ra[i] = *(const float4*)&A [(size_t)(m0 + lr[i]) * lda + k0];
                rb[i] = *(const float4*)&Bm[(size_t)(n0 + lr[i]) * ldb + k0];
            }
        }
        // MMA over this chunk: 2 k-steps of 16
        #pragma unroll
        for (int ks = 0; ks < 2; ks++) {
            const int k = ks * 16;
            uint32_t af[4][4], bf[4][2];
            #pragma unroll
            for (int mi = 0; mi < 4; mi++) {
                const int row = wm + mi * 16 + g;
                af[mi][0] = *(const uint32_t*)&a_s[(row)     * LDSW + k + 2 * tig];
                af[mi][1] = *(const uint32_t*)&a_s[(row + 8) * LDSW + k + 2 * tig];
                af[mi][2] = *(const uint32_t*)&a_s[(row)     * LDSW + k + 2 * tig + 8];
                af[mi][3] = *(const uint32_t*)&a_s[(row + 8) * LDSW + k + 2 * tig + 8];
            }
            #pragma unroll
            for (int ni = 0; ni < 4; ni++) {
                const int col = wn + ni * 8 + g;
                bf[ni][0] = *(const uint32_t*)&b_s[col * LDSW + k + 2 * tig];
                bf[ni][1] = *(const uint32_t*)&b_s[col * LDSW + k + 2 * tig + 8];
            }
            #pragma unroll
            for (int mi = 0; mi < 4; mi++)
                #pragma unroll
                for (int ni = 0; ni < 4; ni++)
                    mma16(acc[mi][ni], af[mi], bf[ni]);
        }
        __syncthreads();
    }

    // ------------------- epilogue (fragment -> gmem, per mode) -------------
    #pragma unroll
    for (int mi = 0; mi < 4; mi++) {
        const int r0 = m0 + wm + mi * 16 + g;     // global row
        const int r1 = r0 + 8;
        #pragma unroll
        for (int ni = 0; ni < 4; ni++) {
            const int cc = n0 + wn + ni * 8 + tig * 2;  // global col (even)
            const float* v = acc[mi][ni];
            if (mode == MODE_SCORES) {
                float* Cb = g_S + (size_t)z * T * T;
                *(float2*)&Cb[(size_t)r0 * T + cc] = make_float2(v[0], v[1]);
                *(float2*)&Cb[(size_t)r1 * T + cc] = make_float2(v[2], v[3]);
            } else if (mode == MODE_PROJ) {
                const int head = n0 >> 8;             // 128-tile inside one head
                const int colh = (n0 & 255) + (cc - n0);
                const int b0_ = r0 >> 11, t0_ = r0 & 2047;
                const int b1_ = r1 >> 11, t1_ = r1 & 2047;
                if (z < 2) {
                    float* Cb = (z == 0) ? g_Q : g_K;
                    float* p0 = &Cb[(((size_t)(b0_ * H + head)) * T + t0_) * KD + colh];
                    float* p1 = &Cb[(((size_t)(b1_ * H + head)) * T + t1_) * KD + colh];
                    *(float2*)p0 = make_float2(v[0] * 0.25f, v[1] * 0.25f);
                    *(float2*)p1 = make_float2(v[2] * 0.25f, v[3] * 0.25f);
                } else {
                    // V transposed: g_Vt[(bh*KD + colh)][t]
                    float* base0 = &g_Vt[(((size_t)(b0_ * H + head)) * KD + colh) * T];
                    float* base1 = &g_Vt[(((size_t)(b1_ * H + head)) * KD + colh) * T];
                    base0[t0_] = v[0]; base0[T + t0_] = v[1];
                    base1[t1_] = v[2]; base1[T + t1_] = v[3];
                }
            } else if (mode == MODE_AV) {
                const int b_ = z >> 3, head = z & 7;
                float* p0 = &g_O[((size_t)(b_ * T + r0)) * NPROJ + head * KD + cc];
                float* p1 = &g_O[((size_t)(b_ * T + r1)) * NPROJ + head * KD + cc];
                *(float2*)p0 = make_float2(v[0], v[1]);
                *(float2*)p1 = make_float2(v[2], v[3]);
            } else {
                const float b0v = pBias[cc], b1v = pBias[cc + 1];
                *(float2*)&pC[(size_t)r0 * KD + cc] = make_float2(v[0] + b0v, v[1] + b1v);
                *(float2*)&pC[(size_t)r1 * KD + cc] = make_float2(v[2] + b0v, v[3] + b1v);
            }
        }
    }
}

// ---------------------------------------------------------------------------
// Weight transposes (one-shot, cheap)
// ---------------------------------------------------------------------------
__global__ void transpose_w(const float* __restrict__ in, int which) {
    // in: [KD=256][NPROJ=2048] -> g_Wt[which]: [2048][256]
    __shared__ float t[32][33];
    float* out = g_Wt + (size_t)which * NPROJ * KD;
    int c0 = blockIdx.x * 32, r0 = blockIdx.y * 32;
    int x = threadIdx.x, y = threadIdx.y;
    #pragma unroll
    for (int i = 0; i < 32; i += 8)
        t[y + i][x] = in[(size_t)(r0 + y + i) * NPROJ + c0 + x];
    __syncthreads();
    #pragma unroll
    for (int i = 0; i < 32; i += 8)
        out[(size_t)(c0 + y + i) * KD + r0 + x] = t[x][y + i];
}
__global__ void transpose_wu(const float* __restrict__ in) {
    // in: [NPROJ=2048][KD=256] -> g_Wut: [256][2048]
    __shared__ float t[32][33];
    int c0 = blockIdx.x * 32, r0 = blockIdx.y * 32;
    int x = threadIdx.x, y = threadIdx.y;
    #pragma unroll
    for (int i = 0; i < 32; i += 8)
        t[y + i][x] = in[(size_t)(r0 + y + i) * KD + c0 + x];
    __syncthreads();
    #pragma unroll
    for (int i = 0; i < 32; i += 8)
        g_Wut[(size_t)(c0 + y + i) * NPROJ + r0 + x] = t[x][y + i];
}

// ---------------------------------------------------------------------------
// Row softmax over S, in place (fp32)
// ---------------------------------------------------------------------------
__device__ __forceinline__ float warpMax(float v) {
    #pragma unroll
    for (int o = 16; o > 0; o >>= 1) v = fmaxf(v, __shfl_xor_sync(0xffffffffu, v, o));
    return v;
}
__device__ __forceinline__ float warpSum(float v) {
    #pragma unroll
    for (int o = 16; o > 0; o >>= 1) v += __shfl_xor_sync(0xffffffffu, v, o);
    return v;
}
__global__ void softmax_kernel() {
    const int row = blockIdx.x, bh = blockIdx.y;
    float* __restrict__ S = g_S + ((size_t)bh * T + row) * T;
    const int tid = threadIdx.x, lane = tid & 31, wid = tid >> 5;
    __shared__ float red[8];

    float vals[8];
    float m = -INFINITY;
    #pragma unroll
    for (int i = 0; i < 8; i++) { vals[i] = S[tid + i * 256]; m = fmaxf(m, vals[i]); }
    m = warpMax(m);
    if (lane == 0) red[wid] = m;
    __syncthreads();
    float bm = red[0];
    #pragma unroll
    for (int w = 1; w < 8; w++) bm = fmaxf(bm, red[w]);

    float s = 0.f;
    #pragma unroll
    for (int i = 0; i < 8; i++) { vals[i] = expf(vals[i] - bm); s += vals[i]; }
    s = warpSum(s);
    __syncthreads();
    if (lane == 0) red[wid] = s;
    __syncthreads();
    float bs = 0.f;
    #pragma unroll
    for (int w = 0; w < 8; w++) bs += red[w];
    const float inv = 1.0f / bs;
    #pragma unroll
    for (int i = 0; i < 8; i++) S[tid + i * 256] = vals[i] * inv;
}

// ---------------------------------------------------------------------------
extern "C" void kernel_launch(void* const* d_in, const int* in_sizes, int n_in,
                              void* d_out, int out_size) {
    const float* x  = (const float*)d_in[0];
    const float* Wq = (const float*)d_in[1];
    const float* Wk = (const float*)d_in[2];
    const float* Wv = (const float*)d_in[3];
    const float* Wu = (const float*)d_in[4];
    const float* bu = (const float*)d_in[5];
    float* out = (float*)d_out;

    cudaFuncSetAttribute(gemm_mma,
                         cudaFuncAttributeMaxDynamicSharedMemorySize, SM_TOTAL);

    // 0) transpose weights to K-major B operands
    transpose_w <<<dim3(NPROJ / 32, KD / 32), dim3(32, 8)>>>(Wq, 0);
    transpose_w <<<dim3(NPROJ / 32, KD / 32), dim3(32, 8)>>>(Wk, 1);
    transpose_w <<<dim3(NPROJ / 32, KD / 32), dim3(32, 8)>>>(Wv, 2);
    transpose_wu<<<dim3(KD / 32, NPROJ / 32), dim3(32, 8)>>>(Wu);

    // 1) projections: [4096,256] @ [256,2048], z = {q,k,v}; V written transposed
    gemm_mma<<<dim3(NPROJ / 128, ROWS / 128, 3), 256, SM_TOTAL>>>(
        MODE_PROJ, x, nullptr, nullptr);

    // 2) S = Q K^T per (b,h)
    gemm_mma<<<dim3(T / 128, T / 128, BH), 256, SM_TOTAL>>>(
        MODE_SCORES, nullptr, nullptr, nullptr);

    // 3) softmax rows
    softmax_kernel<<<dim3(T, BH), 256>>>();

    // 4) O = P V per (b,h) -> [b,t,h*kd]
    gemm_mma<<<dim3(KD / 128, T / 128, BH), 256, SM_TOTAL>>>(
        MODE_AV, nullptr, nullptr, nullptr);

    // 5) out = O @ Wu + bu
    gemm_mma<<<dim3(KD / 128, ROWS / 128, 1), 256, SM_TOTAL>>>(
        MODE_FINAL, nullptr, bu, out);
}

// round 5
// speedup vs baseline: 6.9138x; 1.4901x over previous
#include <cuda_runtime.h>
#include <cuda_fp16.h>
#include <math.h>
#include <stdint.h>

// Problem shape (fixed)
#define B   2
#define T   2048
#define KD  256
#define H   8
#define BH  (B*H)        // 16
#define NPROJ (KD*H)     // 2048
#define ROWS (B*T)       // 4096

// ---------------------------------------------------------------------------
// Scratch (device globals — allocation-free per harness rules)
// ---------------------------------------------------------------------------
__device__ __half g_Qh [BH * T * KD];          // [bh][t][kd] * 0.25, fp16
__device__ __half g_Kh [BH * T * KD];          // [bh][t][kd] * 0.25, fp16
__device__ __half g_Vth[BH * KD * T];          // [bh][kd][t], fp16
__device__ float  g_S  [(size_t)BH * T * T];   // scores fp32 (pre-softmax)
__device__ __half g_P  [(size_t)BH * T * T];   // probs fp16 (post-softmax)
__device__ __half g_Oh [ROWS * NPROJ];         // [b*t][h*kd], fp16
__device__ __half g_Wth [3 * NPROJ * KD];      // Wq^T,Wk^T,Wv^T fp16 [n][k]
__device__ __half g_Wuth[KD * NPROJ];          // Wu^T fp16 [256][2048]

// ---------------------------------------------------------------------------
// Tiling: CTA 128x128, 8 warps 2(m) x 4(n), warp tile 64x32, BK=32.
// Smem row stride 40 halves (80B): ldmatrix phases hit banks
// {0,20,8,28,16,4,24,12} (+const) — conflict-free.
// ---------------------------------------------------------------------------
#define BK    32
#define LDSW  40
#define BUF_HALFS (128 * LDSW)            // 5120 halves = 10240 B
#define SM_TOTAL (4 * BUF_HALFS * 2)      // 40960 B

#define MODE_PROJ   0
#define MODE_SCORES 1
#define MODE_AV     2
#define MODE_FINAL  3

__device__ __forceinline__ uint32_t smem_u32(const void* p) {
    uint32_t a;
    asm("{ .reg .u64 t; cvta.to.shared.u64 t, %1; cvt.u32.u64 %0, t; }"
        : "=r"(a) : "l"(p));
    return a;
}
__device__ __forceinline__ uint32_t packh2(float x, float y) {
    __half2 h = __floats2half2_rn(x, y);
    return *(uint32_t*)&h;
}
#define LDSM_X4(r0, r1, r2, r3, addr) \
    asm volatile("ldmatrix.sync.aligned.m8n8.x4.shared.b16 {%0,%1,%2,%3}, [%4];" \
                 : "=r"(r0), "=r"(r1), "=r"(r2), "=r"(r3) : "r"(addr))

__device__ __forceinline__ void mma16(float c[4], const uint32_t a[4],
                                      const uint32_t b[2]) {
    asm volatile(
        "mma.sync.aligned.m16n8k16.row.col.f32.f16.f16.f32 "
        "{%0,%1,%2,%3}, {%4,%5,%6,%7}, {%8,%9}, {%0,%1,%2,%3};"
        : "+f"(c[0]), "+f"(c[1]), "+f"(c[2]), "+f"(c[3])
        : "r"(a[0]), "r"(a[1]), "r"(a[2]), "r"(a[3]), "r"(b[0]), "r"(b[1]));
}

template <int MODE>
__global__ void __launch_bounds__(256, 2)
gemm_mma(const float* __restrict__ pA,
         const float* __restrict__ pBias, float* __restrict__ pC) {
    extern __shared__ __half smem[];
    __half* sA[2] = { smem,                 smem + BUF_HALFS };
    __half* sB[2] = { smem + 2 * BUF_HALFS, smem + 3 * BUF_HALFS };
    const uint32_t sb0 = smem_u32(smem);
    const uint32_t aB[2] = { sb0, sb0 + BUF_HALFS * 2 };
    const uint32_t bB[2] = { sb0 + 2 * BUF_HALFS * 2, sb0 + 3 * BUF_HALFS * 2 };

    const int tid  = threadIdx.x;
    const int lane = tid & 31, wid = tid >> 5;
    const int g    = lane >> 2, tig = lane & 3;
    const int wm   = (wid & 1) * 64;
    const int wn   = (wid >> 1) * 32;
    const int m0   = blockIdx.y * 128, n0 = blockIdx.x * 128;
    const int z    = blockIdx.z;

    // operands
    const float*  Af = nullptr;   // fp32 A (PROJ only)
    const __half *Ah = nullptr, *Bh = nullptr;
    int lda, ldb, nch;
    if (MODE == MODE_PROJ) {
        Af = pA; lda = KD;
        Bh = g_Wth + (size_t)z * NPROJ * KD; ldb = KD; nch = KD / BK;
    } else if (MODE == MODE_SCORES) {
        Ah = g_Qh + (size_t)z * T * KD; lda = KD;
        Bh = g_Kh + (size_t)z * T * KD; ldb = KD; nch = KD / BK;
    } else if (MODE == MODE_AV) {
        Ah = g_P   + (size_t)z * T * T;  lda = T;
        Bh = g_Vth + (size_t)z * KD * T; ldb = T; nch = T / BK;
    } else {
        Ah = g_Oh;   lda = NPROJ;
        Bh = g_Wuth; ldb = NPROJ;        nch = NPROJ / BK;
    }

    const int lr[4] = { (tid + 0)   >> 3, (tid + 256) >> 3,
                        (tid + 512) >> 3, (tid + 768) >> 3 };
    const int lk = (tid & 7) * 4;   // element offset within 32-elem chunk row

    float acc[4][4][4];
    #pragma unroll
    for (int mi = 0; mi < 4; mi++)
        #pragma unroll
        for (int ni = 0; ni < 4; ni++)
            #pragma unroll
            for (int r = 0; r < 4; r++) acc[mi][ni][r] = 0.f;

    // ldmatrix per-lane byte offsets (row part), constant across chunks
    const int lm_row = lane & 15, lm_k8 = (lane >> 4) * 8;

    float4 fa[4];               // fp32 A prefetch (PROJ)
    uint2  ha[4], hb[4];        // fp16 prefetch
    #pragma unroll
    for (int i = 0; i < 4; i++) {
        if (MODE == MODE_PROJ)
            fa[i] = *(const float4*)&Af[(size_t)(m0 + lr[i]) * lda + lk];
        else
            ha[i] = *(const uint2*)&Ah[(size_t)(m0 + lr[i]) * lda + lk];
        hb[i] = *(const uint2*)&Bh[(size_t)(n0 + lr[i]) * ldb + lk];
    }

    for (int c = 0; c < nch; c++) {
        const int st = c & 1;
        __half* __restrict__ a_s = sA[st];
        __half* __restrict__ b_s = sB[st];
        #pragma unroll
        for (int i = 0; i < 4; i++) {
            if (MODE == MODE_PROJ) {
                uint2 wa = { packh2(fa[i].x, fa[i].y), packh2(fa[i].z, fa[i].w) };
                *(uint2*)&a_s[lr[i] * LDSW + lk] = wa;
            } else {
                *(uint2*)&a_s[lr[i] * LDSW + lk] = ha[i];
            }
            *(uint2*)&b_s[lr[i] * LDSW + lk] = hb[i];
        }
        __syncthreads();
        if (c + 1 < nch) {
            const int k0 = (c + 1) * BK + lk;
            #pragma unroll
            for (int i = 0; i < 4; i++) {
                if (MODE == MODE_PROJ)
                    fa[i] = *(const float4*)&Af[(size_t)(m0 + lr[i]) * lda + k0];
                else
                    ha[i] = *(const uint2*)&Ah[(size_t)(m0 + lr[i]) * lda + k0];
                hb[i] = *(const uint2*)&Bh[(size_t)(n0 + lr[i]) * ldb + k0];
            }
        }
        // MMA: 2 k-steps of 16, fragments via ldmatrix.x4
        #pragma unroll
        for (int ks = 0; ks < 2; ks++) {
            const int k = ks * 16;
            uint32_t af[4][4], bf[4][2];
            #pragma unroll
            for (int mi = 0; mi < 4; mi++) {
                uint32_t ad = aB[st] +
                    (uint32_t)(((wm + mi * 16 + lm_row) * LDSW + k + lm_k8) * 2);
                LDSM_X4(af[mi][0], af[mi][1], af[mi][2], af[mi][3], ad);
            }
            #pragma unroll
            for (int nj = 0; nj < 2; nj++) {
                uint32_t bd = bB[st] +
                    (uint32_t)(((wn + nj * 16 + lm_row) * LDSW + k + lm_k8) * 2);
                LDSM_X4(bf[2 * nj][0], bf[2 * nj + 1][0],
                        bf[2 * nj][1], bf[2 * nj + 1][1], bd);
            }
            #pragma unroll
            for (int mi = 0; mi < 4; mi++)
                #pragma unroll
                for (int ni = 0; ni < 4; ni++)
                    mma16(acc[mi][ni], af[mi], bf[ni]);
        }
        __syncthreads();
    }

    // ------------------- epilogue (per mode) -------------------------------
    #pragma unroll
    for (int mi = 0; mi < 4; mi++) {
        const int r0 = m0 + wm + mi * 16 + g;
        const int r1 = r0 + 8;
        #pragma unroll
        for (int ni = 0; ni < 4; ni++) {
            const int cc = n0 + wn + ni * 8 + tig * 2;
            const float* v = acc[mi][ni];
            if (MODE == MODE_SCORES) {
                float* Cb = g_S + (size_t)z * T * T;
                *(float2*)&Cb[(size_t)r0 * T + cc] = make_float2(v[0], v[1]);
                *(float2*)&Cb[(size_t)r1 * T + cc] = make_float2(v[2], v[3]);
            } else if (MODE == MODE_PROJ) {
                const int head = n0 >> 8;
                const int colh = (n0 & 255) + wn + ni * 8 + tig * 2;
                const int b0_ = r0 >> 11, t0_ = r0 & 2047;
                const int b1_ = r1 >> 11, t1_ = r1 & 2047;
                if (z < 2) {
                    __half* Cb = (z == 0) ? g_Qh : g_Kh;
                    uint32_t p0 = packh2(v[0] * 0.25f, v[1] * 0.25f);
                    uint32_t p1 = packh2(v[2] * 0.25f, v[3] * 0.25f);
                    *(uint32_t*)&Cb[(((size_t)(b0_ * H + head)) * T + t0_) * KD + colh] = p0;
                    *(uint32_t*)&Cb[(((size_t)(b1_ * H + head)) * T + t1_) * KD + colh] = p1;
                } else {
                    __half* base0 = &g_Vth[(((size_t)(b0_ * H + head)) * KD + colh) * T];
                    __half* base1 = &g_Vth[(((size_t)(b1_ * H + head)) * KD + colh) * T];
                    base0[t0_]     = __float2half_rn(v[0]);
                    base0[T + t0_] = __float2half_rn(v[1]);
                    base1[t1_]     = __float2half_rn(v[2]);
                    base1[T + t1_] = __float2half_rn(v[3]);
                }
            } else if (MODE == MODE_AV) {
                const int b_ = z >> 3, head = z & 7;
                *(uint32_t*)&g_Oh[((size_t)(b_ * T + r0)) * NPROJ + head * KD + cc] =
                    packh2(v[0], v[1]);
                *(uint32_t*)&g_Oh[((size_t)(b_ * T + r1)) * NPROJ + head * KD + cc] =
                    packh2(v[2], v[3]);
            } else {
                const float b0v = pBias[cc], b1v = pBias[cc + 1];
                *(float2*)&pC[(size_t)r0 * KD + cc] = make_float2(v[0] + b0v, v[1] + b1v);
                *(float2*)&pC[(size_t)r1 * KD + cc] = make_float2(v[2] + b0v, v[3] + b1v);
            }
        }
    }
}

// ---------------------------------------------------------------------------
// Weight transposes -> fp16 (one-shot, cheap)
// ---------------------------------------------------------------------------
__global__ void transpose_w(const float* __restrict__ in, int which) {
    // in: [KD=256][NPROJ=2048] -> g_Wth[which]: [2048][256] fp16
    __shared__ float t[32][33];
    __half* out = g_Wth + (size_t)which * NPROJ * KD;
    int c0 = blockIdx.x * 32, r0 = blockIdx.y * 32;
    int x = threadIdx.x, y = threadIdx.y;
    #pragma unroll
    for (int i = 0; i < 32; i += 8)
        t[y + i][x] = in[(size_t)(r0 + y + i) * NPROJ + c0 + x];
    __syncthreads();
    #pragma unroll
    for (int i = 0; i < 32; i += 8)
        out[(size_t)(c0 + y + i) * KD + r0 + x] = __float2half_rn(t[x][y + i]);
}
__global__ void transpose_wu(const float* __restrict__ in) {
    // in: [NPROJ=2048][KD=256] -> g_Wuth: [256][2048] fp16
    __shared__ float t[32][33];
    int c0 = blockIdx.x * 32, r0 = blockIdx.y * 32;
    int x = threadIdx.x, y = threadIdx.y;
    #pragma unroll
    for (int i = 0; i < 32; i += 8)
        t[y + i][x] = in[(size_t)(r0 + y + i) * KD + c0 + x];
    __syncthreads();
    #pragma unroll
    for (int i = 0; i < 32; i += 8)
        g_Wuth[(size_t)(c0 + y + i) * NPROJ + r0 + x] = __float2half_rn(t[x][y + i]);
}

// ---------------------------------------------------------------------------
// Row softmax: read fp32 scores, write fp16 probabilities
// ---------------------------------------------------------------------------
__device__ __forceinline__ float warpMax(float v) {
    #pragma unroll
    for (int o = 16; o > 0; o >>= 1) v = fmaxf(v, __shfl_xor_sync(0xffffffffu, v, o));
    return v;
}
__device__ __forceinline__ float warpSum(float v) {
    #pragma unroll
    for (int o = 16; o > 0; o >>= 1) v += __shfl_xor_sync(0xffffffffu, v, o);
    return v;
}
__global__ void softmax_kernel() {
    const int row = blockIdx.x, bh = blockIdx.y;
    const float2* __restrict__ S2 =
        (const float2*)(g_S + ((size_t)bh * T + row) * T);
    __half2* __restrict__ P2 = (__half2*)(g_P + ((size_t)bh * T + row) * T);
    const int tid = threadIdx.x, lane = tid & 31, wid = tid >> 5;
    __shared__ float red[8];

    float2 vals[4];
    float m = -INFINITY;
    #pragma unroll
    for (int i = 0; i < 4; i++) {
        vals[i] = S2[tid + i * 256];
        m = fmaxf(m, fmaxf(vals[i].x, vals[i].y));
    }
    m = warpMax(m);
    if (lane == 0) red[wid] = m;
    __syncthreads();
    float bm = red[0];
    #pragma unroll
    for (int w = 1; w < 8; w++) bm = fmaxf(bm, red[w]);

    float s = 0.f;
    #pragma unroll
    for (int i = 0; i < 4; i++) {
        vals[i].x = __expf(vals[i].x - bm);
        vals[i].y = __expf(vals[i].y - bm);
        s += vals[i].x + vals[i].y;
    }
    s = warpSum(s);
    __syncthreads();
    if (lane == 0) red[wid] = s;
    __syncthreads();
    float bs = 0.f;
    #pragma unroll
    for (int w = 0; w < 8; w++) bs += red[w];
    const float inv = 1.0f / bs;
    #pragma unroll
    for (int i = 0; i < 4; i++)
        P2[tid + i * 256] = __floats2half2_rn(vals[i].x * inv, vals[i].y * inv);
}

// ---------------------------------------------------------------------------
extern "C" void kernel_launch(void* const* d_in, const int* in_sizes, int n_in,
                              void* d_out, int out_size) {
    const float* x  = (const float*)d_in[0];
    const float* Wq = (const float*)d_in[1];
    const float* Wk = (const float*)d_in[2];
    const float* Wv = (const float*)d_in[3];
    const float* Wu = (const float*)d_in[4];
    const float* bu = (const float*)d_in[5];
    float* out = (float*)d_out;

    // 0) transpose weights to fp16 K-major B operands
    transpose_w <<<dim3(NPROJ / 32, KD / 32), dim3(32, 8)>>>(Wq, 0);
    transpose_w <<<dim3(NPROJ / 32, KD / 32), dim3(32, 8)>>>(Wk, 1);
    transpose_w <<<dim3(NPROJ / 32, KD / 32), dim3(32, 8)>>>(Wv, 2);
    transpose_wu<<<dim3(KD / 32, NPROJ / 32), dim3(32, 8)>>>(Wu);

    // 1) projections (z = {q,k,v}); V written transposed; Q,K scaled by 0.25
    gemm_mma<MODE_PROJ><<<dim3(NPROJ / 128, ROWS / 128, 3), 256, SM_TOTAL>>>(
        x, nullptr, nullptr);

    // 2) S = Q K^T per (b,h), fp32 scores
    gemm_mma<MODE_SCORES><<<dim3(T / 128, T / 128, BH), 256, SM_TOTAL>>>(
        nullptr, nullptr, nullptr);

    // 3) softmax rows -> fp16 P
    softmax_kernel<<<dim3(T, BH), 256>>>();

    // 4) O = P V per (b,h) -> fp16 [b,t,h*kd]
    gemm_mma<MODE_AV><<<dim3(KD / 128, T / 128, BH), 256, SM_TOTAL>>>(
        nullptr, nullptr, nullptr);

    // 5) out = O @ Wu + bu (fp32 out)
    gemm_mma<MODE_FINAL><<<dim3(KD / 128, ROWS / 128, 1), 256, SM_TOTAL>>>(
        nullptr, bu, out);
}

// round 6
// speedup vs baseline: 9.8675x; 1.4272x over previous
#include <cuda_runtime.h>
#include <cuda_fp16.h>
#include <math.h>
#include <stdint.h>

// Problem shape (fixed)
#define B   2
#define T   2048
#define KD  256
#define H   8
#define BH  (B*H)        // 16
#define NPROJ (KD*H)     // 2048
#define ROWS (B*T)       // 4096

// ---------------------------------------------------------------------------
// Scratch (device globals — allocation-free per harness rules)
// ---------------------------------------------------------------------------
__device__ __half g_Qh [BH * T * KD];          // [bh][t][kd] * 0.25, fp16
__device__ __half g_Kh [BH * T * KD];          // [bh][t][kd] * 0.25, fp16
__device__ __half g_Vth[BH * KD * T];          // [bh][kd][t], fp16
__device__ __half g_Oh [ROWS * NPROJ];         // [b*t][h*kd], fp16
__device__ __half g_Wth [3 * NPROJ * KD];      // Wq^T,Wk^T,Wv^T fp16 [n][k]
__device__ __half g_Wuth[KD * NPROJ];          // Wu^T fp16 [256][2048]

// ---------------------------------------------------------------------------
// Common PTX helpers
// ---------------------------------------------------------------------------
__device__ __forceinline__ uint32_t smem_u32(const void* p) {
    uint32_t a;
    asm("{ .reg .u64 t; cvta.to.shared.u64 t, %1; cvt.u32.u64 %0, t; }"
        : "=r"(a) : "l"(p));
    return a;
}
__device__ __forceinline__ uint32_t packh2(float x, float y) {
    __half2 h = __floats2half2_rn(x, y);
    return *(uint32_t*)&h;
}
#define LDSM_X4(r0, r1, r2, r3, addr) \
    asm volatile("ldmatrix.sync.aligned.m8n8.x4.shared.b16 {%0,%1,%2,%3}, [%4];" \
                 : "=r"(r0), "=r"(r1), "=r"(r2), "=r"(r3) : "r"(addr))
#define CP_ASYNC16(dst, src) \
    asm volatile("cp.async.ca.shared.global [%0], [%1], 16;" :: "r"(dst), "l"(src))
#define CP_COMMIT() asm volatile("cp.async.commit_group;" ::: "memory")
#define CP_WAIT(n)  asm volatile("cp.async.wait_group %0;" :: "n"(n) : "memory")

__device__ __forceinline__ void mma16(float c[4], const uint32_t a[4],
                                      const uint32_t b[2]) {
    asm volatile(
        "mma.sync.aligned.m16n8k16.row.col.f32.f16.f16.f32 "
        "{%0,%1,%2,%3}, {%4,%5,%6,%7}, {%8,%9}, {%0,%1,%2,%3};"
        : "+f"(c[0]), "+f"(c[1]), "+f"(c[2]), "+f"(c[3])
        : "r"(a[0]), "r"(a[1]), "r"(a[2]), "r"(a[3]), "r"(b[0]), "r"(b[1]));
}

// ===========================================================================
// GEMM engine (proj + final only now)
// ===========================================================================
#define BK    32
#define LDSW  40
#define BUF_HALFS (128 * LDSW)
#define SM_GEMM (4 * BUF_HALFS * 2)       // 40960 B

#define MODE_PROJ   0
#define MODE_FINAL  3

template <int MODE>
__global__ void __launch_bounds__(256, 2)
gemm_mma(const float* __restrict__ pA,
         const float* __restrict__ pBias, float* __restrict__ pC) {
    extern __shared__ __half smem[];
    __half* sA[2] = { smem,                 smem + BUF_HALFS };
    __half* sB[2] = { smem + 2 * BUF_HALFS, smem + 3 * BUF_HALFS };
    const uint32_t sb0 = smem_u32(smem);
    const uint32_t aB[2] = { sb0, sb0 + BUF_HALFS * 2 };
    const uint32_t bB[2] = { sb0 + 2 * BUF_HALFS * 2, sb0 + 3 * BUF_HALFS * 2 };

    const int tid  = threadIdx.x;
    const int lane = tid & 31, wid = tid >> 5;
    const int g    = lane >> 2, tig = lane & 3;
    const int wm   = (wid & 1) * 64;
    const int wn   = (wid >> 1) * 32;
    const int m0   = blockIdx.y * 128, n0 = blockIdx.x * 128;
    const int z    = blockIdx.z;

    const float*  Af = nullptr;
    const __half *Ah = nullptr, *Bh = nullptr;
    int lda, ldb, nch;
    if (MODE == MODE_PROJ) {
        Af = pA; lda = KD;
        Bh = g_Wth + (size_t)z * NPROJ * KD; ldb = KD; nch = KD / BK;
    } else {
        Ah = g_Oh;   lda = NPROJ;
        Bh = g_Wuth; ldb = NPROJ;        nch = NPROJ / BK;
    }

    const int lr[4] = { (tid + 0)   >> 3, (tid + 256) >> 3,
                        (tid + 512) >> 3, (tid + 768) >> 3 };
    const int lk = (tid & 7) * 4;

    float acc[4][4][4];
    #pragma unroll
    for (int mi = 0; mi < 4; mi++)
        #pragma unroll
        for (int ni = 0; ni < 4; ni++)
            #pragma unroll
            for (int r = 0; r < 4; r++) acc[mi][ni][r] = 0.f;

    const int lm_row = lane & 15, lm_k8 = (lane >> 4) * 8;

    float4 fa[4];
    uint2  ha[4], hb[4];
    #pragma unroll
    for (int i = 0; i < 4; i++) {
        if (MODE == MODE_PROJ)
            fa[i] = *(const float4*)&Af[(size_t)(m0 + lr[i]) * lda + lk];
        else
            ha[i] = *(const uint2*)&Ah[(size_t)(m0 + lr[i]) * lda + lk];
        hb[i] = *(const uint2*)&Bh[(size_t)(n0 + lr[i]) * ldb + lk];
    }

    for (int c = 0; c < nch; c++) {
        const int st = c & 1;
        __half* __restrict__ a_s = sA[st];
        __half* __restrict__ b_s = sB[st];
        #pragma unroll
        for (int i = 0; i < 4; i++) {
            if (MODE == MODE_PROJ) {
                uint2 wa = { packh2(fa[i].x, fa[i].y), packh2(fa[i].z, fa[i].w) };
                *(uint2*)&a_s[lr[i] * LDSW + lk] = wa;
            } else {
                *(uint2*)&a_s[lr[i] * LDSW + lk] = ha[i];
            }
            *(uint2*)&b_s[lr[i] * LDSW + lk] = hb[i];
        }
        __syncthreads();
        if (c + 1 < nch) {
            const int k0 = (c + 1) * BK + lk;
            #pragma unroll
            for (int i = 0; i < 4; i++) {
                if (MODE == MODE_PROJ)
                    fa[i] = *(const float4*)&Af[(size_t)(m0 + lr[i]) * lda + k0];
                else
                    ha[i] = *(const uint2*)&Ah[(size_t)(m0 + lr[i]) * lda + k0];
                hb[i] = *(const uint2*)&Bh[(size_t)(n0 + lr[i]) * ldb + k0];
            }
        }
        #pragma unroll
        for (int ks = 0; ks < 2; ks++) {
            const int k = ks * 16;
            uint32_t af[4][4], bf[4][2];
            #pragma unroll
            for (int mi = 0; mi < 4; mi++) {
                uint32_t ad = aB[st] +
                    (uint32_t)(((wm + mi * 16 + lm_row) * LDSW + k + lm_k8) * 2);
                LDSM_X4(af[mi][0], af[mi][1], af[mi][2], af[mi][3], ad);
            }
            #pragma unroll
            for (int nj = 0; nj < 2; nj++) {
                uint32_t bd = bB[st] +
                    (uint32_t)(((wn + nj * 16 + lm_row) * LDSW + k + lm_k8) * 2);
                LDSM_X4(bf[2 * nj][0], bf[2 * nj + 1][0],
                        bf[2 * nj][1], bf[2 * nj + 1][1], bd);
            }
            #pragma unroll
            for (int mi = 0; mi < 4; mi++)
                #pragma unroll
                for (int ni = 0; ni < 4; ni++)
                    mma16(acc[mi][ni], af[mi], bf[ni]);
        }
        __syncthreads();
    }

    #pragma unroll
    for (int mi = 0; mi < 4; mi++) {
        const int r0 = m0 + wm + mi * 16 + g;
        const int r1 = r0 + 8;
        #pragma unroll
        for (int ni = 0; ni < 4; ni++) {
            const int cc = n0 + wn + ni * 8 + tig * 2;
            const float* v = acc[mi][ni];
            if (MODE == MODE_PROJ) {
                const int head = n0 >> 8;
                const int colh = (n0 & 255) + wn + ni * 8 + tig * 2;
                const int b0_ = r0 >> 11, t0_ = r0 & 2047;
                const int b1_ = r1 >> 11, t1_ = r1 & 2047;
                if (z < 2) {
                    __half* Cb = (z == 0) ? g_Qh : g_Kh;
                    *(uint32_t*)&Cb[(((size_t)(b0_ * H + head)) * T + t0_) * KD + colh] =
                        packh2(v[0] * 0.25f, v[1] * 0.25f);
                    *(uint32_t*)&Cb[(((size_t)(b1_ * H + head)) * T + t1_) * KD + colh] =
                        packh2(v[2] * 0.25f, v[3] * 0.25f);
                } else {
                    __half* base0 = &g_Vth[(((size_t)(b0_ * H + head)) * KD + colh) * T];
                    __half* base1 = &g_Vth[(((size_t)(b1_ * H + head)) * KD + colh) * T];
                    base0[t0_]     = __float2half_rn(v[0]);
                    base0[T + t0_] = __float2half_rn(v[1]);
                    base1[t1_]     = __float2half_rn(v[2]);
                    base1[T + t1_] = __float2half_rn(v[3]);
                }
            } else {
                const float b0v = pBias[cc], b1v = pBias[cc + 1];
                *(float2*)&pC[(size_t)r0 * KD + cc] = make_float2(v[0] + b0v, v[1] + b1v);
                *(float2*)&pC[(size_t)r1 * KD + cc] = make_float2(v[2] + b0v, v[3] + b1v);
            }
        }
    }
}

// ===========================================================================
// Fused flash attention: per (bh, 128-row q tile); K/V streamed in 64-key
// chunks with cp.async double buffering; online softmax; O accum in regs.
// ===========================================================================
#define FK   64                        // keys per chunk
#define NCH  (T / FK)                  // 32 chunks
#define LQ   264                       // Q smem row stride (halves)
#define LK   264                       // K smem row stride
#define LV   72                        // V smem row stride
#define SMQ_BYTES (128 * LQ * 2)       // 67584
#define SMK_BYTES (FK * LK * 2)        // 33792 per buffer
#define SMV_BYTES (256 * LV * 2)       // 36864 per buffer
#define SM_FLASH (SMQ_BYTES + 2 * SMK_BYTES + 2 * SMV_BYTES)   // 208896

__global__ void __launch_bounds__(256, 1)
flash_kernel() {
    extern __shared__ __half sm[];
    const uint32_t sb = smem_u32(sm);
    const uint32_t sQ = sb;
    const uint32_t sK[2] = { sb + SMQ_BYTES, sb + SMQ_BYTES + SMK_BYTES };
    const uint32_t sV[2] = { sb + SMQ_BYTES + 2 * SMK_BYTES,
                             sb + SMQ_BYTES + 2 * SMK_BYTES + SMV_BYTES };

    const int tid = threadIdx.x;
    const int lane = tid & 31, wid = tid >> 5;
    const int g = lane >> 2, tig = lane & 3;
    const int lm_row = lane & 15, lm_k8 = (lane >> 4) * 8;

    const int q0 = blockIdx.x * 128;
    const int bh = blockIdx.y;
    const __half* __restrict__ Qg = g_Qh + ((size_t)bh * T + q0) * KD;
    const __half* __restrict__ Kg = g_Kh + (size_t)bh * T * KD;
    const __half* __restrict__ Vg = g_Vth + (size_t)bh * KD * T;

    // ---- async loads ----
    // Q: 128 rows x 256 halves; 16 x 16B per thread
    {
        #pragma unroll
        for (int i = 0; i < 16; i++) {
            int idx = tid + i * 256;
            int r = idx >> 5, c = idx & 31;
            CP_ASYNC16(sQ + (uint32_t)((r * LQ + c * 8) * 2), Qg + r * KD + c * 8);
        }
    }
    // K chunk loader: 64 rows x 256 halves, 8 x 16B per thread
    // V chunk loader: 256 rows x 64 halves, 8 x 16B per thread
    auto issue_kv = [&](int ch, int buf) {
        const int s0 = ch * FK;
        #pragma unroll
        for (int i = 0; i < 8; i++) {
            int idx = tid + i * 256;
            int r = idx >> 5, c = idx & 31;
            CP_ASYNC16(sK[buf] + (uint32_t)((r * LK + c * 8) * 2),
                       Kg + (size_t)(s0 + r) * KD + c * 8);
        }
        #pragma unroll
        for (int i = 0; i < 8; i++) {
            int idx = tid + i * 256;
            int r = idx >> 3, c = idx & 7;
            CP_ASYNC16(sV[buf] + (uint32_t)((r * LV + c * 8) * 2),
                       Vg + (size_t)r * T + s0 + c * 8);
        }
    };

    issue_kv(0, 0);
    CP_COMMIT();              // group: Q + chunk0
    issue_kv(1, 1);
    CP_COMMIT();              // group: chunk1

    // ---- state ----
    float oacc[32][4];
    #pragma unroll
    for (int n = 0; n < 32; n++)
        #pragma unroll
        for (int r = 0; r < 4; r++) oacc[n][r] = 0.f;
    float m0 = -INFINITY, m1 = -INFINITY;
    float l0 = 0.f, l1 = 0.f;

    const uint32_t qrow_base = sQ + (uint32_t)(((wid * 16 + lm_row) * LQ + lm_k8) * 2);

    for (int ch = 0; ch < NCH; ch++) {
        if (ch < NCH - 1) CP_WAIT(1); else CP_WAIT(0);
        __syncthreads();
        const int buf = ch & 1;

        // ---- S = Q K^T  (16 q-rows x 64 keys per warp) ----
        float sacc[8][4];
        #pragma unroll
        for (int n = 0; n < 8; n++)
            #pragma unroll
            for (int r = 0; r < 4; r++) sacc[n][r] = 0.f;

        #pragma unroll
        for (int ks = 0; ks < 16; ks++) {
            uint32_t a[4];
            LDSM_X4(a[0], a[1], a[2], a[3], qrow_base + (uint32_t)(ks * 32));
            uint32_t bf[8][2];
            #pragma unroll
            for (int nj = 0; nj < 4; nj++) {
                uint32_t bd = sK[buf] +
                    (uint32_t)(((nj * 16 + lm_row) * LK + ks * 16 + lm_k8) * 2);
                LDSM_X4(bf[2 * nj][0], bf[2 * nj + 1][0],
                        bf[2 * nj][1], bf[2 * nj + 1][1], bd);
            }
            #pragma unroll
            for (int nt = 0; nt < 8; nt++) mma16(sacc[nt], a, bf[nt]);
        }

        // ---- online softmax ----
        float cm0 = -INFINITY, cm1 = -INFINITY;
        #pragma unroll
        for (int nt = 0; nt < 8; nt++) {
            cm0 = fmaxf(cm0, fmaxf(sacc[nt][0], sacc[nt][1]));
            cm1 = fmaxf(cm1, fmaxf(sacc[nt][2], sacc[nt][3]));
        }
        cm0 = fmaxf(cm0, __shfl_xor_sync(0xffffffffu, cm0, 1));
        cm0 = fmaxf(cm0, __shfl_xor_sync(0xffffffffu, cm0, 2));
        cm1 = fmaxf(cm1, __shfl_xor_sync(0xffffffffu, cm1, 1));
        cm1 = fmaxf(cm1, __shfl_xor_sync(0xffffffffu, cm1, 2));

        const float mn0 = fmaxf(m0, cm0), mn1 = fmaxf(m1, cm1);
        const float al0 = __expf(m0 - mn0), al1 = __expf(m1 - mn1);
        m0 = mn0; m1 = mn1;

        float rs0 = 0.f, rs1 = 0.f;
        #pragma unroll
        for (int nt = 0; nt < 8; nt++) {
            sacc[nt][0] = __expf(sacc[nt][0] - mn0);
            sacc[nt][1] = __expf(sacc[nt][1] - mn0);
            sacc[nt][2] = __expf(sacc[nt][2] - mn1);
            sacc[nt][3] = __expf(sacc[nt][3] - mn1);
            rs0 += sacc[nt][0] + sacc[nt][1];
            rs1 += sacc[nt][2] + sacc[nt][3];
        }
        rs0 += __shfl_xor_sync(0xffffffffu, rs0, 1);
        rs0 += __shfl_xor_sync(0xffffffffu, rs0, 2);
        rs1 += __shfl_xor_sync(0xffffffffu, rs1, 1);
        rs1 += __shfl_xor_sync(0xffffffffu, rs1, 2);
        l0 = l0 * al0 + rs0;
        l1 = l1 * al1 + rs1;

        #pragma unroll
        for (int n = 0; n < 32; n++) {
            oacc[n][0] *= al0; oacc[n][1] *= al0;
            oacc[n][2] *= al1; oacc[n][3] *= al1;
        }

        // pack P (C-layout == A-layout identity)
        uint32_t pa[4][4];
        #pragma unroll
        for (int ks2 = 0; ks2 < 4; ks2++) {
            pa[ks2][0] = packh2(sacc[2 * ks2][0],     sacc[2 * ks2][1]);
            pa[ks2][1] = packh2(sacc[2 * ks2][2],     sacc[2 * ks2][3]);
            pa[ks2][2] = packh2(sacc[2 * ks2 + 1][0], sacc[2 * ks2 + 1][1]);
            pa[ks2][3] = packh2(sacc[2 * ks2 + 1][2], sacc[2 * ks2 + 1][3]);
        }

        // ---- O += P V  (k=64 in 4 steps; n=256 in two 16-tile halves) ----
        #pragma unroll
        for (int ks2 = 0; ks2 < 4; ks2++) {
            #pragma unroll
            for (int hv = 0; hv < 2; hv++) {
                uint32_t bv[16][2];
                #pragma unroll
                for (int nj = 0; nj < 8; nj++) {
                    uint32_t bd = sV[buf] +
                        (uint32_t)((((hv * 8 + nj) * 16 + lm_row) * LV +
                                    ks2 * 16 + lm_k8) * 2);
                    LDSM_X4(bv[2 * nj][0], bv[2 * nj + 1][0],
                            bv[2 * nj][1], bv[2 * nj + 1][1], bd);
                }
                #pragma unroll
                for (int nt = 0; nt < 16; nt++)
                    mma16(oacc[hv * 16 + nt], pa[ks2], bv[nt]);
            }
        }

        __syncthreads();
        if (ch + 2 < NCH) { issue_kv(ch + 2, buf); CP_COMMIT(); }
    }

    // ---- epilogue: normalize and store fp16 O ----
    const float inv0 = 1.0f / l0, inv1 = 1.0f / l1;
    const int r0 = q0 + wid * 16 + g, r1 = r0 + 8;
    const int b_ = bh >> 3, head = bh & 7;
    __half* o0 = g_Oh + ((size_t)(b_ * T + r0)) * NPROJ + head * KD;
    __half* o1 = g_Oh + ((size_t)(b_ * T + r1)) * NPROJ + head * KD;
    #pragma unroll
    for (int nt = 0; nt < 32; nt++) {
        const int col = nt * 8 + tig * 2;
        *(uint32_t*)&o0[col] = packh2(oacc[nt][0] * inv0, oacc[nt][1] * inv0);
        *(uint32_t*)&o1[col] = packh2(oacc[nt][2] * inv1, oacc[nt][3] * inv1);
    }
}

// ---------------------------------------------------------------------------
// Weight transposes -> fp16 (one-shot, cheap)
// ---------------------------------------------------------------------------
__global__ void transpose_w(const float* __restrict__ in, int which) {
    __shared__ float t[32][33];
    __half* out = g_Wth + (size_t)which * NPROJ * KD;
    int c0 = blockIdx.x * 32, r0 = blockIdx.y * 32;
    int x = threadIdx.x, y = threadIdx.y;
    #pragma unroll
    for (int i = 0; i < 32; i += 8)
        t[y + i][x] = in[(size_t)(r0 + y + i) * NPROJ + c0 + x];
    __syncthreads();
    #pragma unroll
    for (int i = 0; i < 32; i += 8)
        out[(size_t)(c0 + y + i) * KD + r0 + x] = __float2half_rn(t[x][y + i]);
}
__global__ void transpose_wu(const float* __restrict__ in) {
    __shared__ float t[32][33];
    int c0 = blockIdx.x * 32, r0 = blockIdx.y * 32;
    int x = threadIdx.x, y = threadIdx.y;
    #pragma unroll
    for (int i = 0; i < 32; i += 8)
        t[y + i][x] = in[(size_t)(r0 + y + i) * KD + c0 + x];
    __syncthreads();
    #pragma unroll
    for (int i = 0; i < 32; i += 8)
        g_Wuth[(size_t)(c0 + y + i) * NPROJ + r0 + x] = __float2half_rn(t[x][y + i]);
}

// ---------------------------------------------------------------------------
extern "C" void kernel_launch(void* const* d_in, const int* in_sizes, int n_in,
                              void* d_out, int out_size) {
    const float* x  = (const float*)d_in[0];
    const float* Wq = (const float*)d_in[1];
    const float* Wk = (const float*)d_in[2];
    const float* Wv = (const float*)d_in[3];
    const float* Wu = (const float*)d_in[4];
    const float* bu = (const float*)d_in[5];
    float* out = (float*)d_out;

    cudaFuncSetAttribute(flash_kernel,
                         cudaFuncAttributeMaxDynamicSharedMemorySize, SM_FLASH);

    // 0) transpose weights to fp16 K-major B operands
    transpose_w <<<dim3(NPROJ / 32, KD / 32), dim3(32, 8)>>>(Wq, 0);
    transpose_w <<<dim3(NPROJ / 32, KD / 32), dim3(32, 8)>>>(Wk, 1);
    transpose_w <<<dim3(NPROJ / 32, KD / 32), dim3(32, 8)>>>(Wv, 2);
    transpose_wu<<<dim3(KD / 32, NPROJ / 32), dim3(32, 8)>>>(Wu);

    // 1) projections (z = {q,k,v}); V transposed; Q,K scaled by 0.25
    gemm_mma<MODE_PROJ><<<dim3(NPROJ / 128, ROWS / 128, 3), 256, SM_GEMM>>>(
        x, nullptr, nullptr);

    // 2) fused attention: softmax(Q K^T) V -> g_Oh
    flash_kernel<<<dim3(T / 128, BH), 256, SM_FLASH>>>();

    // 3) out = O @ Wu + bu (fp32 out)
    gemm_mma<MODE_FINAL><<<dim3(KD / 128, ROWS / 128, 1), 256, SM_GEMM>>>(
        nullptr, bu, out);
}

// round 7
// speedup vs baseline: 9.8954x; 1.0028x over previous
#include <cuda_runtime.h>
#include <cuda_fp16.h>
#include <math.h>
#include <stdint.h>

// Problem shape (fixed)
#define B   2
#define T   2048
#define KD  256
#define H   8
#define BH  (B*H)        // 16
#define NPROJ (KD*H)     // 2048
#define ROWS (B*T)       // 4096

#define LOG2E 1.4426950408889634f

// ---------------------------------------------------------------------------
// Scratch (device globals — allocation-free per harness rules)
// ---------------------------------------------------------------------------
__device__ __half g_Xh [ROWS * KD];            // x in fp16
__device__ __half g_Qh [BH * T * KD];          // [bh][t][kd] * 0.25*log2e
__device__ __half g_Kh [BH * T * KD];          // [bh][t][kd] * 0.25
__device__ __half g_Vth[BH * KD * T];          // [bh][kd][t]
__device__ __half g_Oh [ROWS * NPROJ];         // [b*t][h*kd]
__device__ __half g_Wth [3 * NPROJ * KD];      // Wq^T,Wk^T,Wv^T fp16 [n][k]
__device__ __half g_Wuth[KD * NPROJ];          // Wu^T fp16 [256][2048]

// ---------------------------------------------------------------------------
// Common PTX helpers
// ---------------------------------------------------------------------------
__device__ __forceinline__ uint32_t smem_u32(const void* p) {
    uint32_t a;
    asm("{ .reg .u64 t; cvta.to.shared.u64 t, %1; cvt.u32.u64 %0, t; }"
        : "=r"(a) : "l"(p));
    return a;
}
__device__ __forceinline__ uint32_t packh2(float x, float y) {
    __half2 h = __floats2half2_rn(x, y);
    return *(uint32_t*)&h;
}
#define LDSM_X4(r0, r1, r2, r3, addr) \
    asm volatile("ldmatrix.sync.aligned.m8n8.x4.shared.b16 {%0,%1,%2,%3}, [%4];" \
                 : "=r"(r0), "=r"(r1), "=r"(r2), "=r"(r3) : "r"(addr))
#define CP_ASYNC16(dst, src) \
    asm volatile("cp.async.ca.shared.global [%0], [%1], 16;" :: "r"(dst), "l"(src))
#define CP_COMMIT() asm volatile("cp.async.commit_group;" ::: "memory")
#define CP_WAIT(n)  asm volatile("cp.async.wait_group %0;" :: "n"(n) : "memory")

__device__ __forceinline__ void mma16(float c[4], const uint32_t a[4],
                                      const uint32_t b[2]) {
    asm volatile(
        "mma.sync.aligned.m16n8k16.row.col.f32.f16.f16.f32 "
        "{%0,%1,%2,%3}, {%4,%5,%6,%7}, {%8,%9}, {%0,%1,%2,%3};"
        : "+f"(c[0]), "+f"(c[1]), "+f"(c[2]), "+f"(c[3])
        : "r"(a[0]), "r"(a[1]), "r"(a[2]), "r"(a[3]), "r"(b[0]), "r"(b[1]));
}

// ===========================================================================
// GEMM engine (proj + final)
// ===========================================================================
#define BK    32
#define LDSW  40
#define BUF_HALFS (128 * LDSW)
#define SM_GEMM (4 * BUF_HALFS * 2)       // 40960 B

#define MODE_PROJ   0
#define MODE_FINAL  3

template <int MODE>
__global__ void __launch_bounds__(256, 2)
gemm_mma(const float* __restrict__ pBias, float* __restrict__ pC) {
    extern __shared__ __half smem[];
    __half* sA[2] = { smem,                 smem + BUF_HALFS };
    __half* sB[2] = { smem + 2 * BUF_HALFS, smem + 3 * BUF_HALFS };
    const uint32_t sb0 = smem_u32(smem);
    const uint32_t aB[2] = { sb0, sb0 + BUF_HALFS * 2 };
    const uint32_t bB[2] = { sb0 + 2 * BUF_HALFS * 2, sb0 + 3 * BUF_HALFS * 2 };

    const int tid  = threadIdx.x;
    const int lane = tid & 31, wid = tid >> 5;
    const int g    = lane >> 2, tig = lane & 3;
    const int wm   = (wid & 1) * 64;
    const int wn   = (wid >> 1) * 32;
    const int m0   = blockIdx.y * 128, n0 = blockIdx.x * 128;
    const int z    = blockIdx.z;

    const __half *Ah, *Bh;
    int lda, ldb, nch;
    if (MODE == MODE_PROJ) {
        Ah = g_Xh; lda = KD;
        Bh = g_Wth + (size_t)z * NPROJ * KD; ldb = KD; nch = KD / BK;
    } else {
        Ah = g_Oh;   lda = NPROJ;
        Bh = g_Wuth; ldb = NPROJ;        nch = NPROJ / BK;
    }

    const int lr[4] = { (tid + 0)   >> 3, (tid + 256) >> 3,
                        (tid + 512) >> 3, (tid + 768) >> 3 };
    const int lk = (tid & 7) * 4;

    float acc[4][4][4];
    #pragma unroll
    for (int mi = 0; mi < 4; mi++)
        #pragma unroll
        for (int ni = 0; ni < 4; ni++)
            #pragma unroll
            for (int r = 0; r < 4; r++) acc[mi][ni][r] = 0.f;

    const int lm_row = lane & 15, lm_k8 = (lane >> 4) * 8;

    uint2 ha[4], hb[4];
    #pragma unroll
    for (int i = 0; i < 4; i++) {
        ha[i] = *(const uint2*)&Ah[(size_t)(m0 + lr[i]) * lda + lk];
        hb[i] = *(const uint2*)&Bh[(size_t)(n0 + lr[i]) * ldb + lk];
    }

    for (int c = 0; c < nch; c++) {
        const int st = c & 1;
        __half* __restrict__ a_s = sA[st];
        __half* __restrict__ b_s = sB[st];
        #pragma unroll
        for (int i = 0; i < 4; i++) {
            *(uint2*)&a_s[lr[i] * LDSW + lk] = ha[i];
            *(uint2*)&b_s[lr[i] * LDSW + lk] = hb[i];
        }
        __syncthreads();
        if (c + 1 < nch) {
            const int k0 = (c + 1) * BK + lk;
            #pragma unroll
            for (int i = 0; i < 4; i++) {
                ha[i] = *(const uint2*)&Ah[(size_t)(m0 + lr[i]) * lda + k0];
                hb[i] = *(const uint2*)&Bh[(size_t)(n0 + lr[i]) * ldb + k0];
            }
        }
        #pragma unroll
        for (int ks = 0; ks < 2; ks++) {
            const int k = ks * 16;
            uint32_t af[4][4], bf[4][2];
            #pragma unroll
            for (int mi = 0; mi < 4; mi++) {
                uint32_t ad = aB[st] +
                    (uint32_t)(((wm + mi * 16 + lm_row) * LDSW + k + lm_k8) * 2);
                LDSM_X4(af[mi][0], af[mi][1], af[mi][2], af[mi][3], ad);
            }
            #pragma unroll
            for (int nj = 0; nj < 2; nj++) {
                uint32_t bd = bB[st] +
                    (uint32_t)(((wn + nj * 16 + lm_row) * LDSW + k + lm_k8) * 2);
                LDSM_X4(bf[2 * nj][0], bf[2 * nj + 1][0],
                        bf[2 * nj][1], bf[2 * nj + 1][1], bd);
            }
            #pragma unroll
            for (int mi = 0; mi < 4; mi++)
                #pragma unroll
                for (int ni = 0; ni < 4; ni++)
                    mma16(acc[mi][ni], af[mi], bf[ni]);
        }
        __syncthreads();
    }

    // ------------------- epilogue -------------------------------
    if (MODE == MODE_PROJ && z == 2) {
        // V: stage transposed tile in smem, then coalesced column writes.
        // epi[col][row], stride 136 halves. Needs 128*136*2 = 34816 B <= SM_GEMM.
        __half* epi = smem;
        #pragma unroll
        for (int mi = 0; mi < 4; mi++) {
            const int rl0 = wm + mi * 16 + g;
            #pragma unroll
            for (int ni = 0; ni < 4; ni++) {
                const int cl = wn + ni * 8 + tig * 2;
                const float* v = acc[mi][ni];
                epi[(cl)     * 136 + rl0]     = __float2half_rn(v[0]);
                epi[(cl + 1) * 136 + rl0]     = __float2half_rn(v[1]);
                epi[(cl)     * 136 + rl0 + 8] = __float2half_rn(v[2]);
                epi[(cl + 1) * 136 + rl0 + 8] = __float2half_rn(v[3]);
            }
        }
        __syncthreads();
        const int head = n0 >> 8;
        const int colh0 = n0 & 255;
        const int b_ = m0 >> 11, t0 = m0 & 2047;
        const int col = tid >> 1, sub = tid & 1;
        __half* dst = g_Vth + (((size_t)(b_ * H + head)) * KD + colh0 + col) * T + t0;
        #pragma unroll
        for (int j = 0; j < 8; j++) {
            const int row = sub * 8 + j * 16;
            *(uint4*)&dst[row] = *(const uint4*)&epi[col * 136 + row];
        }
        return;
    }

    #pragma unroll
    for (int mi = 0; mi < 4; mi++) {
        const int r0 = m0 + wm + mi * 16 + g;
        const int r1 = r0 + 8;
        #pragma unroll
        for (int ni = 0; ni < 4; ni++) {
            const int cc = n0 + wn + ni * 8 + tig * 2;
            const float* v = acc[mi][ni];
            if (MODE == MODE_PROJ) {
                const int head = n0 >> 8;
                const int colh = (n0 & 255) + wn + ni * 8 + tig * 2;
                const int b0_ = r0 >> 11, t0_ = r0 & 2047;
                const int b1_ = r1 >> 11, t1_ = r1 & 2047;
                // z==0: Q with 0.25*log2e (exp2-domain softmax); z==1: K with 0.25
                const float scale = (z == 0) ? 0.25f * LOG2E : 0.25f;
                __half* Cb = (z == 0) ? g_Qh : g_Kh;
                *(uint32_t*)&Cb[(((size_t)(b0_ * H + head)) * T + t0_) * KD + colh] =
                    packh2(v[0] * scale, v[1] * scale);
                *(uint32_t*)&Cb[(((size_t)(b1_ * H + head)) * T + t1_) * KD + colh] =
                    packh2(v[2] * scale, v[3] * scale);
            } else {
                const float b0v = pBias[cc], b1v = pBias[cc + 1];
                *(float2*)&pC[(size_t)r0 * KD + cc] = make_float2(v[0] + b0v, v[1] + b1v);
                *(float2*)&pC[(size_t)r1 * KD + cc] = make_float2(v[2] + b0v, v[3] + b1v);
            }
        }
    }
}

// ===========================================================================
// Fused flash attention (scores in log2 domain; exp2-based online softmax)
// ===========================================================================
#define FK   64                        // keys per chunk
#define NCH  (T / FK)                  // 32 chunks
#define LQ   264
#define LK   264
#define LV   72
#define SMQ_BYTES (128 * LQ * 2)
#define SMK_BYTES (FK * LK * 2)
#define SMV_BYTES (256 * LV * 2)
#define SM_FLASH (SMQ_BYTES + 2 * SMK_BYTES + 2 * SMV_BYTES)   // 208896

__global__ void __launch_bounds__(256, 1)
flash_kernel() {
    extern __shared__ __half sm[];
    const uint32_t sb = smem_u32(sm);
    const uint32_t sQ = sb;
    const uint32_t sK[2] = { sb + SMQ_BYTES, sb + SMQ_BYTES + SMK_BYTES };
    const uint32_t sV[2] = { sb + SMQ_BYTES + 2 * SMK_BYTES,
                             sb + SMQ_BYTES + 2 * SMK_BYTES + SMV_BYTES };

    const int tid = threadIdx.x;
    const int lane = tid & 31, wid = tid >> 5;
    const int g = lane >> 2, tig = lane & 3;
    const int lm_row = lane & 15, lm_k8 = (lane >> 4) * 8;

    const int q0 = blockIdx.x * 128;
    const int bh = blockIdx.y;
    const __half* __restrict__ Qg = g_Qh + ((size_t)bh * T + q0) * KD;
    const __half* __restrict__ Kg = g_Kh + (size_t)bh * T * KD;
    const __half* __restrict__ Vg = g_Vth + (size_t)bh * KD * T;

    {
        #pragma unroll
        for (int i = 0; i < 16; i++) {
            int idx = tid + i * 256;
            int r = idx >> 5, c = idx & 31;
            CP_ASYNC16(sQ + (uint32_t)((r * LQ + c * 8) * 2), Qg + r * KD + c * 8);
        }
    }
    auto issue_kv = [&](int ch, int buf) {
        const int s0 = ch * FK;
        #pragma unroll
        for (int i = 0; i < 8; i++) {
            int idx = tid + i * 256;
            int r = idx >> 5, c = idx & 31;
            CP_ASYNC16(sK[buf] + (uint32_t)((r * LK + c * 8) * 2),
                       Kg + (size_t)(s0 + r) * KD + c * 8);
        }
        #pragma unroll
        for (int i = 0; i < 8; i++) {
            int idx = tid + i * 256;
            int r = idx >> 3, c = idx & 7;
            CP_ASYNC16(sV[buf] + (uint32_t)((r * LV + c * 8) * 2),
                       Vg + (size_t)r * T + s0 + c * 8);
        }
    };

    issue_kv(0, 0);
    CP_COMMIT();
    issue_kv(1, 1);
    CP_COMMIT();

    float oacc[32][4];
    #pragma unroll
    for (int n = 0; n < 32; n++)
        #pragma unroll
        for (int r = 0; r < 4; r++) oacc[n][r] = 0.f;
    float m0 = -INFINITY, m1 = -INFINITY;
    float l0 = 0.f, l1 = 0.f;

    const uint32_t qrow_base = sQ + (uint32_t)(((wid * 16 + lm_row) * LQ + lm_k8) * 2);

    for (int ch = 0; ch < NCH; ch++) {
        if (ch < NCH - 1) CP_WAIT(1); else CP_WAIT(0);
        __syncthreads();
        const int buf = ch & 1;

        // ---- S = Q K^T (log2-domain scores) ----
        float sacc[8][4];
        #pragma unroll
        for (int n = 0; n < 8; n++)
            #pragma unroll
            for (int r = 0; r < 4; r++) sacc[n][r] = 0.f;

        #pragma unroll
        for (int ks = 0; ks < 16; ks++) {
            uint32_t a[4];
            LDSM_X4(a[0], a[1], a[2], a[3], qrow_base + (uint32_t)(ks * 32));
            uint32_t bf[8][2];
            #pragma unroll
            for (int nj = 0; nj < 4; nj++) {
                uint32_t bd = sK[buf] +
                    (uint32_t)(((nj * 16 + lm_row) * LK + ks * 16 + lm_k8) * 2);
                LDSM_X4(bf[2 * nj][0], bf[2 * nj + 1][0],
                        bf[2 * nj][1], bf[2 * nj + 1][1], bd);
            }
            #pragma unroll
            for (int nt = 0; nt < 8; nt++) mma16(sacc[nt], a, bf[nt]);
        }

        // ---- online softmax (base-2) ----
        float cm0 = -INFINITY, cm1 = -INFINITY;
        #pragma unroll
        for (int nt = 0; nt < 8; nt++) {
            cm0 = fmaxf(cm0, fmaxf(sacc[nt][0], sacc[nt][1]));
            cm1 = fmaxf(cm1, fmaxf(sacc[nt][2], sacc[nt][3]));
        }
        cm0 = fmaxf(cm0, __shfl_xor_sync(0xffffffffu, cm0, 1));
        cm0 = fmaxf(cm0, __shfl_xor_sync(0xffffffffu, cm0, 2));
        cm1 = fmaxf(cm1, __shfl_xor_sync(0xffffffffu, cm1, 1));
        cm1 = fmaxf(cm1, __shfl_xor_sync(0xffffffffu, cm1, 2));

        const float mn0 = fmaxf(m0, cm0), mn1 = fmaxf(m1, cm1);
        const float al0 = exp2f(m0 - mn0), al1 = exp2f(m1 - mn1);
        m0 = mn0; m1 = mn1;

        float rs0 = 0.f, rs1 = 0.f;
        #pragma unroll
        for (int nt = 0; nt < 8; nt++) {
            sacc[nt][0] = exp2f(sacc[nt][0] - mn0);
            sacc[nt][1] = exp2f(sacc[nt][1] - mn0);
            sacc[nt][2] = exp2f(sacc[nt][2] - mn1);
            sacc[nt][3] = exp2f(sacc[nt][3] - mn1);
            rs0 += sacc[nt][0] + sacc[nt][1];
            rs1 += sacc[nt][2] + sacc[nt][3];
        }
        rs0 += __shfl_xor_sync(0xffffffffu, rs0, 1);
        rs0 += __shfl_xor_sync(0xffffffffu, rs0, 2);
        rs1 += __shfl_xor_sync(0xffffffffu, rs1, 1);
        rs1 += __shfl_xor_sync(0xffffffffu, rs1, 2);
        l0 = l0 * al0 + rs0;
        l1 = l1 * al1 + rs1;

        #pragma unroll
        for (int n = 0; n < 32; n++) {
            oacc[n][0] *= al0; oacc[n][1] *= al0;
            oacc[n][2] *= al1; oacc[n][3] *= al1;
        }

        uint32_t pa[4][4];
        #pragma unroll
        for (int ks2 = 0; ks2 < 4; ks2++) {
            pa[ks2][0] = packh2(sacc[2 * ks2][0],     sacc[2 * ks2][1]);
            pa[ks2][1] = packh2(sacc[2 * ks2][2],     sacc[2 * ks2][3]);
            pa[ks2][2] = packh2(sacc[2 * ks2 + 1][0], sacc[2 * ks2 + 1][1]);
            pa[ks2][3] = packh2(sacc[2 * ks2 + 1][2], sacc[2 * ks2 + 1][3]);
        }

        #pragma unroll
        for (int ks2 = 0; ks2 < 4; ks2++) {
            #pragma unroll
            for (int hv = 0; hv < 2; hv++) {
                uint32_t bv[16][2];
                #pragma unroll
                for (int nj = 0; nj < 8; nj++) {
                    uint32_t bd = sV[buf] +
                        (uint32_t)((((hv * 8 + nj) * 16 + lm_row) * LV +
                                    ks2 * 16 + lm_k8) * 2);
                    LDSM_X4(bv[2 * nj][0], bv[2 * nj + 1][0],
                            bv[2 * nj][1], bv[2 * nj + 1][1], bd);
                }
                #pragma unroll
                for (int nt = 0; nt < 16; nt++)
                    mma16(oacc[hv * 16 + nt], pa[ks2], bv[nt]);
            }
        }

        __syncthreads();
        if (ch + 2 < NCH) { issue_kv(ch + 2, buf); CP_COMMIT(); }
    }

    const float inv0 = 1.0f / l0, inv1 = 1.0f / l1;
    const int r0 = q0 + wid * 16 + g, r1 = r0 + 8;
    const int b_ = bh >> 3, head = bh & 7;
    __half* o0 = g_Oh + ((size_t)(b_ * T + r0)) * NPROJ + head * KD;
    __half* o1 = g_Oh + ((size_t)(b_ * T + r1)) * NPROJ + head * KD;
    #pragma unroll
    for (int nt = 0; nt < 32; nt++) {
        const int col = nt * 8 + tig * 2;
        *(uint32_t*)&o0[col] = packh2(oacc[nt][0] * inv0, oacc[nt][1] * inv0);
        *(uint32_t*)&o1[col] = packh2(oacc[nt][2] * inv1, oacc[nt][3] * inv1);
    }
}

// ---------------------------------------------------------------------------
// One-shot prep kernels
// ---------------------------------------------------------------------------
__global__ void convert_x(const float* __restrict__ in) {
    // ROWS*KD = 1,048,576 elements; 512 blocks x 256 threads x 8 elems
    const int base = (blockIdx.x * 256 + threadIdx.x) * 8;
    float4 a = *(const float4*)&in[base];
    float4 b = *(const float4*)&in[base + 4];
    uint2 w0 = { packh2(a.x, a.y), packh2(a.z, a.w) };
    uint2 w1 = { packh2(b.x, b.y), packh2(b.z, b.w) };
    *(uint2*)&g_Xh[base]     = w0;
    *(uint2*)&g_Xh[base + 4] = w1;
}
__global__ void transpose_w(const float* __restrict__ in, int which) {
    __shared__ float t[32][33];
    __half* out = g_Wth + (size_t)which * NPROJ * KD;
    int c0 = blockIdx.x * 32, r0 = blockIdx.y * 32;
    int x = threadIdx.x, y = threadIdx.y;
    #pragma unroll
    for (int i = 0; i < 32; i += 8)
        t[y + i][x] = in[(size_t)(r0 + y + i) * NPROJ + c0 + x];
    __syncthreads();
    #pragma unroll
    for (int i = 0; i < 32; i += 8)
        out[(size_t)(c0 + y + i) * KD + r0 + x] = __float2half_rn(t[x][y + i]);
}
__global__ void transpose_wu(const float* __restrict__ in) {
    __shared__ float t[32][33];
    int c0 = blockIdx.x * 32, r0 = blockIdx.y * 32;
    int x = threadIdx.x, y = threadIdx.y;
    #pragma unroll
    for (int i = 0; i < 32; i += 8)
        t[y + i][x] = in[(size_t)(r0 + y + i) * KD + c0 + x];
    __syncthreads();
    #pragma unroll
    for (int i = 0; i < 32; i += 8)
        g_Wuth[(size_t)(c0 + y + i) * NPROJ + r0 + x] = __float2half_rn(t[x][y + i]);
}

// ---------------------------------------------------------------------------
extern "C" void kernel_launch(void* const* d_in, const int* in_sizes, int n_in,
                              void* d_out, int out_size) {
    const float* x  = (const float*)d_in[0];
    const float* Wq = (const float*)d_in[1];
    const float* Wk = (const float*)d_in[2];
    const float* Wv = (const float*)d_in[3];
    const float* Wu = (const float*)d_in[4];
    const float* bu = (const float*)d_in[5];
    float* out = (float*)d_out;

    cudaFuncSetAttribute(flash_kernel,
                         cudaFuncAttributeMaxDynamicSharedMemorySize, SM_FLASH);

    // 0) fp16 conversions / weight transposes
    convert_x<<<512, 256>>>(x);
    transpose_w <<<dim3(NPROJ / 32, KD / 32), dim3(32, 8)>>>(Wq, 0);
    transpose_w <<<dim3(NPROJ / 32, KD / 32), dim3(32, 8)>>>(Wk, 1);
    transpose_w <<<dim3(NPROJ / 32, KD / 32), dim3(32, 8)>>>(Wv, 2);
    transpose_wu<<<dim3(KD / 32, NPROJ / 32), dim3(32, 8)>>>(Wu);

    // 1) projections (z = {q,k,v}); V transposed via smem; Q has log2e folded
    gemm_mma<MODE_PROJ><<<dim3(NPROJ / 128, ROWS / 128, 3), 256, SM_GEMM>>>(
        nullptr, nullptr);

    // 2) fused attention -> g_Oh
    flash_kernel<<<dim3(T / 128, BH), 256, SM_FLASH>>>();

    // 3) out = O @ Wu + bu (fp32)
    gemm_mma<MODE_FINAL><<<dim3(KD / 128, ROWS / 128, 1), 256, SM_GEMM>>>(
        bu, out);
}

// round 9
// speedup vs baseline: 11.3271x; 1.1447x over previous
#include <cuda_runtime.h>
#include <cuda_fp16.h>
#include <math.h>
#include <stdint.h>

// Problem shape (fixed)
#define B   2
#define T   2048
#define KD  256
#define H   8
#define BH  (B*H)        // 16
#define NPROJ (KD*H)     // 2048
#define ROWS (B*T)       // 4096

#define LOG2E 1.4426950408889634f

// ---------------------------------------------------------------------------
// Scratch (device globals — allocation-free per harness rules)
// ---------------------------------------------------------------------------
__device__ __half g_Xh [ROWS * KD];            // x in fp16
__device__ __half g_Qh [BH * T * KD];          // [bh][t][kd] * 0.25*log2e
__device__ __half g_Kh [BH * T * KD];          // [bh][t][kd] * 0.25
__device__ __half g_Vth[BH * KD * T];          // [bh][kd][t]
__device__ __half g_Oh [ROWS * NPROJ];         // [b*t][h*kd]
__device__ __half g_Wth [3 * NPROJ * KD];      // Wq^T,Wk^T,Wv^T fp16 [n][k]
__device__ __half g_Wuth[KD * NPROJ];          // Wu^T fp16 [256][2048]

// ---------------------------------------------------------------------------
// Common PTX helpers
// ---------------------------------------------------------------------------
__device__ __forceinline__ uint32_t smem_u32(const void* p) {
    uint32_t a;
    asm("{ .reg .u64 t; cvta.to.shared.u64 t, %1; cvt.u32.u64 %0, t; }"
        : "=r"(a) : "l"(p));
    return a;
}
__device__ __forceinline__ uint32_t packh2(float x, float y) {
    __half2 h = __floats2half2_rn(x, y);
    return *(uint32_t*)&h;
}
#define LDSM_X4(r0, r1, r2, r3, addr) \
    asm volatile("ldmatrix.sync.aligned.m8n8.x4.shared.b16 {%0,%1,%2,%3}, [%4];" \
                 : "=r"(r0), "=r"(r1), "=r"(r2), "=r"(r3) : "r"(addr))
#define CP_ASYNC16(dst, src) \
    asm volatile("cp.async.cg.shared.global [%0], [%1], 16;" :: "r"(dst), "l"(src))
#define CP_COMMIT() asm volatile("cp.async.commit_group;" ::: "memory")
#define CP_WAIT(n)  asm volatile("cp.async.wait_group %0;" :: "n"(n) : "memory")

__device__ __forceinline__ void mma16(float c[4], const uint32_t a[4],
                                      const uint32_t b[2]) {
    asm volatile(
        "mma.sync.aligned.m16n8k16.row.col.f32.f16.f16.f32 "
        "{%0,%1,%2,%3}, {%4,%5,%6,%7}, {%8,%9}, {%0,%1,%2,%3};"
        : "+f"(c[0]), "+f"(c[1]), "+f"(c[2]), "+f"(c[3])
        : "r"(a[0]), "r"(a[1]), "r"(a[2]), "r"(a[3]), "r"(b[0]), "r"(b[1]));
}

// ===========================================================================
// GEMM engine (proj + final) — cp.async double-buffered mainloop
// ===========================================================================
#define BK    32
#define LDSW  40
#define BUF_HALFS (128 * LDSW)
#define SM_GEMM (4 * BUF_HALFS * 2)       // 40960 B

#define MODE_PROJ   0
#define MODE_FINAL  3

template <int MODE>
__global__ void __launch_bounds__(256, 2)
gemm_mma(const float* __restrict__ pBias, float* __restrict__ pC) {
    extern __shared__ __half smem[];
    const uint32_t sb0 = smem_u32(smem);
    const uint32_t aB[2] = { sb0, sb0 + BUF_HALFS * 2 };
    const uint32_t bB[2] = { sb0 + 2 * BUF_HALFS * 2, sb0 + 3 * BUF_HALFS * 2 };

    const int tid  = threadIdx.x;
    const int lane = tid & 31, wid = tid >> 5;
    const int g    = lane >> 2, tig = lane & 3;
    const int wm   = (wid & 1) * 64;
    const int wn   = (wid >> 1) * 32;
    const int m0   = blockIdx.y * 128, n0 = blockIdx.x * 128;
    const int z    = blockIdx.z;

    const __half *Ah, *Bh;
    int lda, ldb, nch;
    if (MODE == MODE_PROJ) {
        Ah = g_Xh; lda = KD;
        Bh = g_Wth + (size_t)z * NPROJ * KD; ldb = KD; nch = KD / BK;
    } else {
        Ah = g_Oh;   lda = NPROJ;
        Bh = g_Wuth; ldb = NPROJ;        nch = NPROJ / BK;
    }

    // cp.async mapping: 512 16B-units per operand per chunk, 2 per thread
    const int cr[2] = { (tid + 0) >> 2, (tid + 256) >> 2 };
    const int c8 = (tid & 3) * 8;          // halves offset within 32-half row

    auto issue_chunk = [&](int c, int st) {
        const int k0 = c * BK;
        #pragma unroll
        for (int i = 0; i < 2; i++) {
            CP_ASYNC16(aB[st] + (uint32_t)((cr[i] * LDSW + c8) * 2),
                       &Ah[(size_t)(m0 + cr[i]) * lda + k0 + c8]);
            CP_ASYNC16(bB[st] + (uint32_t)((cr[i] * LDSW + c8) * 2),
                       &Bh[(size_t)(n0 + cr[i]) * ldb + k0 + c8]);
        }
    };

    float acc[4][4][4];
    #pragma unroll
    for (int mi = 0; mi < 4; mi++)
        #pragma unroll
        for (int ni = 0; ni < 4; ni++)
            #pragma unroll
            for (int r = 0; r < 4; r++) acc[mi][ni][r] = 0.f;

    const int lm_row = lane & 15, lm_k8 = (lane >> 4) * 8;

    issue_chunk(0, 0); CP_COMMIT();
    issue_chunk(1, 1); CP_COMMIT();

    for (int c = 0; c < nch; c++) {
        const int st = c & 1;
        if (c + 1 < nch) CP_WAIT(1); else CP_WAIT(0);
        __syncthreads();
        #pragma unroll
        for (int ks = 0; ks < 2; ks++) {
            const int k = ks * 16;
            uint32_t af[4][4], bf[4][2];
            #pragma unroll
            for (int mi = 0; mi < 4; mi++) {
                uint32_t ad = aB[st] +
                    (uint32_t)(((wm + mi * 16 + lm_row) * LDSW + k + lm_k8) * 2);
                LDSM_X4(af[mi][0], af[mi][1], af[mi][2], af[mi][3], ad);
            }
            #pragma unroll
            for (int nj = 0; nj < 2; nj++) {
                uint32_t bd = bB[st] +
                    (uint32_t)(((wn + nj * 16 + lm_row) * LDSW + k + lm_k8) * 2);
                LDSM_X4(bf[2 * nj][0], bf[2 * nj + 1][0],
                        bf[2 * nj][1], bf[2 * nj + 1][1], bd);
            }
            #pragma unroll
            for (int mi = 0; mi < 4; mi++)
                #pragma unroll
                for (int ni = 0; ni < 4; ni++)
                    mma16(acc[mi][ni], af[mi], bf[ni]);
        }
        __syncthreads();
        if (c + 2 < nch) { issue_chunk(c + 2, st); CP_COMMIT(); }
    }

    // ------------------- epilogue -------------------------------
    if (MODE == MODE_PROJ && z == 2) {
        // V: stage transposed tile in smem, then coalesced column writes.
        __half* epi = smem;
        #pragma unroll
        for (int mi = 0; mi < 4; mi++) {
            const int rl0 = wm + mi * 16 + g;
            #pragma unroll
            for (int ni = 0; ni < 4; ni++) {
                const int cl = wn + ni * 8 + tig * 2;
                const float* v = acc[mi][ni];
                epi[(cl)     * 136 + rl0]     = __float2half_rn(v[0]);
                epi[(cl + 1) * 136 + rl0]     = __float2half_rn(v[1]);
                epi[(cl)     * 136 + rl0 + 8] = __float2half_rn(v[2]);
                epi[(cl + 1) * 136 + rl0 + 8] = __float2half_rn(v[3]);
            }
        }
        __syncthreads();
        const int head = n0 >> 8;
        const int colh0 = n0 & 255;
        const int b_ = m0 >> 11, t0 = m0 & 2047;
        const int col = tid >> 1, sub = tid & 1;
        __half* dst = g_Vth + (((size_t)(b_ * H + head)) * KD + colh0 + col) * T + t0;
        #pragma unroll
        for (int j = 0; j < 8; j++) {
            const int row = sub * 8 + j * 16;
            *(uint4*)&dst[row] = *(const uint4*)&epi[col * 136 + row];
        }
        return;
    }

    #pragma unroll
    for (int mi = 0; mi < 4; mi++) {
        const int r0 = m0 + wm + mi * 16 + g;
        const int r1 = r0 + 8;
        #pragma unroll
        for (int ni = 0; ni < 4; ni++) {
            const int cc = n0 + wn + ni * 8 + tig * 2;
            const float* v = acc[mi][ni];
            if (MODE == MODE_PROJ) {
                const int head = n0 >> 8;
                const int colh = (n0 & 255) + wn + ni * 8 + tig * 2;
                const int b0_ = r0 >> 11, t0_ = r0 & 2047;
                const int b1_ = r1 >> 11, t1_ = r1 & 2047;
                const float scale = (z == 0) ? 0.25f * LOG2E : 0.25f;
                __half* Cb = (z == 0) ? g_Qh : g_Kh;
                *(uint32_t*)&Cb[(((size_t)(b0_ * H + head)) * T + t0_) * KD + colh] =
                    packh2(v[0] * scale, v[1] * scale);
                *(uint32_t*)&Cb[(((size_t)(b1_ * H + head)) * T + t1_) * KD + colh] =
                    packh2(v[2] * scale, v[3] * scale);
            } else {
                const float b0v = pBias[cc], b1v = pBias[cc + 1];
                *(float2*)&pC[(size_t)r0 * KD + cc] = make_float2(v[0] + b0v, v[1] + b1v);
                *(float2*)&pC[(size_t)r1 * KD + cc] = make_float2(v[2] + b0v, v[3] + b1v);
            }
        }
    }
}

// ===========================================================================
// Fused flash attention — exp2 softmax interleaved with PV MMA
// ===========================================================================
#define FK   64                        // keys per chunk
#define NCH  (T / FK)                  // 32 chunks
#define LQ   264
#define LK   264
#define LV   72
#define SMQ_BYTES (128 * LQ * 2)
#define SMK_BYTES (FK * LK * 2)
#define SMV_BYTES (256 * LV * 2)
#define SM_FLASH (SMQ_BYTES + 2 * SMK_BYTES + 2 * SMV_BYTES)   // 208896

__global__ void __launch_bounds__(256, 1)
flash_kernel() {
    extern __shared__ __half sm[];
    const uint32_t sb = smem_u32(sm);
    const uint32_t sQ = sb;
    const uint32_t sK[2] = { sb + SMQ_BYTES, sb + SMQ_BYTES + SMK_BYTES };
    const uint32_t sV[2] = { sb + SMQ_BYTES + 2 * SMK_BYTES,
                             sb + SMQ_BYTES + 2 * SMK_BYTES + SMV_BYTES };

    const int tid = threadIdx.x;
    const int lane = tid & 31, wid = tid >> 5;
    const int g = lane >> 2, tig = lane & 3;
    const int lm_row = lane & 15, lm_k8 = (lane >> 4) * 8;

    const int q0 = blockIdx.x * 128;
    const int bh = blockIdx.y;
    const __half* __restrict__ Qg = g_Qh + ((size_t)bh * T + q0) * KD;
    const __half* __restrict__ Kg = g_Kh + (size_t)bh * T * KD;
    const __half* __restrict__ Vg = g_Vth + (size_t)bh * KD * T;

    {
        #pragma unroll
        for (int i = 0; i < 16; i++) {
            int idx = tid + i * 256;
            int r = idx >> 5, c = idx & 31;
            CP_ASYNC16(sQ + (uint32_t)((r * LQ + c * 8) * 2), Qg + r * KD + c * 8);
        }
    }
    auto issue_kv = [&](int ch, int buf) {
        const int s0 = ch * FK;
        #pragma unroll
        for (int i = 0; i < 8; i++) {
            int idx = tid + i * 256;
            int r = idx >> 5, c = idx & 31;
            CP_ASYNC16(sK[buf] + (uint32_t)((r * LK + c * 8) * 2),
                       Kg + (size_t)(s0 + r) * KD + c * 8);
        }
        #pragma unroll
        for (int i = 0; i < 8; i++) {
            int idx = tid + i * 256;
            int r = idx >> 3, c = idx & 7;
            CP_ASYNC16(sV[buf] + (uint32_t)((r * LV + c * 8) * 2),
                       Vg + (size_t)r * T + s0 + c * 8);
        }
    };

    issue_kv(0, 0);
    CP_COMMIT();
    issue_kv(1, 1);
    CP_COMMIT();

    float oacc[32][4];
    #pragma unroll
    for (int n = 0; n < 32; n++)
        #pragma unroll
        for (int r = 0; r < 4; r++) oacc[n][r] = 0.f;
    float m0 = -INFINITY, m1 = -INFINITY;
    float l0 = 0.f, l1 = 0.f;

    const uint32_t qrow_base = sQ + (uint32_t)(((wid * 16 + lm_row) * LQ + lm_k8) * 2);

    for (int ch = 0; ch < NCH; ch++) {
        if (ch < NCH - 1) CP_WAIT(1); else CP_WAIT(0);
        __syncthreads();
        const int buf = ch & 1;

        // ---- S = Q K^T (log2-domain scores) ----
        float sacc[8][4];
        #pragma unroll
        for (int n = 0; n < 8; n++)
            #pragma unroll
            for (int r = 0; r < 4; r++) sacc[n][r] = 0.f;

        #pragma unroll
        for (int ks = 0; ks < 16; ks++) {
            uint32_t a[4];
            LDSM_X4(a[0], a[1], a[2], a[3], qrow_base + (uint32_t)(ks * 32));
            uint32_t bf[8][2];
            #pragma unroll
            for (int nj = 0; nj < 4; nj++) {
                uint32_t bd = sK[buf] +
                    (uint32_t)(((nj * 16 + lm_row) * LK + ks * 16 + lm_k8) * 2);
                LDSM_X4(bf[2 * nj][0], bf[2 * nj + 1][0],
                        bf[2 * nj][1], bf[2 * nj + 1][1], bd);
            }
            #pragma unroll
            for (int nt = 0; nt < 8; nt++) mma16(sacc[nt], a, bf[nt]);
        }

        // ---- max reduction + rescale (serial part, minimized) ----
        float cm0 = -INFINITY, cm1 = -INFINITY;
        #pragma unroll
        for (int nt = 0; nt < 8; nt++) {
            cm0 = fmaxf(cm0, fmaxf(sacc[nt][0], sacc[nt][1]));
            cm1 = fmaxf(cm1, fmaxf(sacc[nt][2], sacc[nt][3]));
        }
        cm0 = fmaxf(cm0, __shfl_xor_sync(0xffffffffu, cm0, 1));
        cm0 = fmaxf(cm0, __shfl_xor_sync(0xffffffffu, cm0, 2));
        cm1 = fmaxf(cm1, __shfl_xor_sync(0xffffffffu, cm1, 1));
        cm1 = fmaxf(cm1, __shfl_xor_sync(0xffffffffu, cm1, 2));

        const float mn0 = fmaxf(m0, cm0), mn1 = fmaxf(m1, cm1);
        const float al0 = exp2f(m0 - mn0), al1 = exp2f(m1 - mn1);
        m0 = mn0; m1 = mn1;

        #pragma unroll
        for (int n = 0; n < 32; n++) {
            oacc[n][0] *= al0; oacc[n][1] *= al0;
            oacc[n][2] *= al1; oacc[n][3] *= al1;
        }

        // ---- interleaved: exp/pack k-step ks2, then its PV MMAs ----
        float rs0 = 0.f, rs1 = 0.f;
        #pragma unroll
        for (int ks2 = 0; ks2 < 4; ks2++) {
            const int e0 = 2 * ks2, e1 = 2 * ks2 + 1;
            sacc[e0][0] = exp2f(sacc[e0][0] - mn0);
            sacc[e0][1] = exp2f(sacc[e0][1] - mn0);
            sacc[e0][2] = exp2f(sacc[e0][2] - mn1);
            sacc[e0][3] = exp2f(sacc[e0][3] - mn1);
            sacc[e1][0] = exp2f(sacc[e1][0] - mn0);
            sacc[e1][1] = exp2f(sacc[e1][1] - mn0);
            sacc[e1][2] = exp2f(sacc[e1][2] - mn1);
            sacc[e1][3] = exp2f(sacc[e1][3] - mn1);
            rs0 += sacc[e0][0] + sacc[e0][1] + sacc[e1][0] + sacc[e1][1];
            rs1 += sacc[e0][2] + sacc[e0][3] + sacc[e1][2] + sacc[e1][3];

            uint32_t pa[4];
            pa[0] = packh2(sacc[e0][0], sacc[e0][1]);
            pa[1] = packh2(sacc[e0][2], sacc[e0][3]);
            pa[2] = packh2(sacc[e1][0], sacc[e1][1]);
            pa[3] = packh2(sacc[e1][2], sacc[e1][3]);

            #pragma unroll
            for (int hv = 0; hv < 2; hv++) {
                uint32_t bv[16][2];
                #pragma unroll
                for (int nj = 0; nj < 8; nj++) {
                    uint32_t bd = sV[buf] +
                        (uint32_t)((((hv * 8 + nj) * 16 + lm_row) * LV +
                                    ks2 * 16 + lm_k8) * 2);
                    LDSM_X4(bv[2 * nj][0], bv[2 * nj + 1][0],
                            bv[2 * nj][1], bv[2 * nj + 1][1], bd);
                }
                #pragma unroll
                for (int nt = 0; nt < 16; nt++)
                    mma16(oacc[hv * 16 + nt], pa, bv[nt]);
            }
        }

        rs0 += __shfl_xor_sync(0xffffffffu, rs0, 1);
        rs0 += __shfl_xor_sync(0xffffffffu, rs0, 2);
        rs1 += __shfl_xor_sync(0xffffffffu, rs1, 1);
        rs1 += __shfl_xor_sync(0xffffffffu, rs1, 2);
        l0 = l0 * al0 + rs0;
        l1 = l1 * al1 + rs1;

        __syncthreads();
        if (ch + 2 < NCH) { issue_kv(ch + 2, buf); CP_COMMIT(); }
    }

    const float inv0 = 1.0f / l0, inv1 = 1.0f / l1;
    const int r0 = q0 + wid * 16 + g, r1 = r0 + 8;
    const int b_ = bh >> 3, head = bh & 7;
    __half* o0 = g_Oh + ((size_t)(b_ * T + r0)) * NPROJ + head * KD;
    __half* o1 = g_Oh + ((size_t)(b_ * T + r1)) * NPROJ + head * KD;
    #pragma unroll
    for (int nt = 0; nt < 32; nt++) {
        const int col = nt * 8 + tig * 2;
        *(uint32_t*)&o0[col] = packh2(oacc[nt][0] * inv0, oacc[nt][1] * inv0);
        *(uint32_t*)&o1[col] = packh2(oacc[nt][2] * inv1, oacc[nt][3] * inv1);
    }
}

// ---------------------------------------------------------------------------
// One-shot prep kernels
// ---------------------------------------------------------------------------
__global__ void convert_x(const float* __restrict__ in) {
    const int base = (blockIdx.x * 256 + threadIdx.x) * 8;
    float4 a = *(const float4*)&in[base];
    float4 b = *(const float4*)&in[base + 4];
    uint2 w0 = { packh2(a.x, a.y), packh2(a.z, a.w) };
    uint2 w1 = { packh2(b.x, b.y), packh2(b.z, b.w) };
    *(uint2*)&g_Xh[base]     = w0;
    *(uint2*)&g_Xh[base + 4] = w1;
}
__global__ void transpose_w(const float* __restrict__ in, int which) {
    __shared__ float t[32][33];
    __half* out = g_Wth + (size_t)which * NPROJ * KD;
    int c0 = blockIdx.x * 32, r0 = blockIdx.y * 32;
    int x = threadIdx.x, y = threadIdx.y;
    #pragma unroll
    for (int i = 0; i < 32; i += 8)
        t[y + i][x] = in[(size_t)(r0 + y + i) * NPROJ + c0 + x];
    __syncthreads();
    #pragma unroll
    for (int i = 0; i < 32; i += 8)
        out[(size_t)(c0 + y + i) * KD + r0 + x] = __float2half_rn(t[x][y + i]);
}
__global__ void transpose_wu(const float* __restrict__ in) {
    __shared__ float t[32][33];
    int c0 = blockIdx.x * 32, r0 = blockIdx.y * 32;
    int x = threadIdx.x, y = threadIdx.y;
    #pragma unroll
    for (int i = 0; i < 32; i += 8)
        t[y + i][x] = in[(size_t)(r0 + y + i) * KD + c0 + x];
    __syncthreads();
    #pragma unroll
    for (int i = 0; i < 32; i += 8)
        g_Wuth[(size_t)(c0 + y + i) * NPROJ + r0 + x] = __float2half_rn(t[x][y + i]);
}

// ---------------------------------------------------------------------------
extern "C" void kernel_launch(void* const* d_in, const int* in_sizes, int n_in,
                              void* d_out, int out_size) {
    const float* x  = (const float*)d_in[0];
    const float* Wq = (const float*)d_in[1];
    const float* Wk = (const float*)d_in[2];
    const float* Wv = (const float*)d_in[3];
    const float* Wu = (const float*)d_in[4];
    const float* bu = (const float*)d_in[5];
    float* out = (float*)d_out;

    cudaFuncSetAttribute(flash_kernel,
                         cudaFuncAttributeMaxDynamicSharedMemorySize, SM_FLASH);

    // 0) fp16 conversions / weight transposes
    convert_x<<<512, 256>>>(x);
    transpose_w <<<dim3(NPROJ / 32, KD / 32), dim3(32, 8)>>>(Wq, 0);
    transpose_w <<<dim3(NPROJ / 32, KD / 32), dim3(32, 8)>>>(Wk, 1);
    transpose_w <<<dim3(NPROJ / 32, KD / 32), dim3(32, 8)>>>(Wv, 2);
    transpose_wu<<<dim3(KD / 32, NPROJ / 32), dim3(32, 8)>>>(Wu);

    // 1) projections (z = {q,k,v}); V transposed via smem; Q has log2e folded
    gemm_mma<MODE_PROJ><<<dim3(NPROJ / 128, ROWS / 128, 3), 256, SM_GEMM>>>(
        nullptr, nullptr);

    // 2) fused attention -> g_Oh
    flash_kernel<<<dim3(T / 128, BH), 256, SM_FLASH>>>();

    // 3) out = O @ Wu + bu (fp32)
    gemm_mma<MODE_FINAL><<<dim3(KD / 128, ROWS / 128, 1), 256, SM_GEMM>>>(
        bu, out);
}

// round 10
// speedup vs baseline: 11.8940x; 1.0500x over previous
#include <cuda_runtime.h>
#include <cuda_fp16.h>
#include <math.h>
#include <stdint.h>

// Problem shape (fixed)
#define B   2
#define T   2048
#define KD  256
#define H   8
#define BH  (B*H)        // 16
#define NPROJ (KD*H)     // 2048
#define ROWS (B*T)       // 4096

#define LOG2E 1.4426950408889634f

// ---------------------------------------------------------------------------
// Scratch (device globals — allocation-free per harness rules)
// ---------------------------------------------------------------------------
__device__ __half g_Xh [ROWS * KD];            // x in fp16
__device__ __half g_Qh [BH * T * KD];          // [bh][t][kd] * 0.25*log2e
__device__ __half g_Kh [BH * T * KD];          // [bh][t][kd] * 0.25
__device__ __half g_Vth[BH * KD * T];          // [bh][kd][t]
__device__ __half g_Oh [ROWS * NPROJ];         // [b*t][h*kd]
__device__ __half g_Wth [3 * NPROJ * KD];      // Wq^T,Wk^T,Wv^T fp16 [n][k]
__device__ __half g_Wuth[KD * NPROJ];          // Wu^T fp16 [256][2048]

// ---------------------------------------------------------------------------
// Common PTX helpers
// ---------------------------------------------------------------------------
__device__ __forceinline__ uint32_t smem_u32(const void* p) {
    uint32_t a;
    asm("{ .reg .u64 t; cvta.to.shared.u64 t, %1; cvt.u32.u64 %0, t; }"
        : "=r"(a) : "l"(p));
    return a;
}
__device__ __forceinline__ uint32_t packh2(float x, float y) {
    __half2 h = __floats2half2_rn(x, y);
    return *(uint32_t*)&h;
}
#define LDSM_X4(r0, r1, r2, r3, addr) \
    asm volatile("ldmatrix.sync.aligned.m8n8.x4.shared.b16 {%0,%1,%2,%3}, [%4];" \
                 : "=r"(r0), "=r"(r1), "=r"(r2), "=r"(r3) : "r"(addr))
#define CP_ASYNC16(dst, src) \
    asm volatile("cp.async.cg.shared.global [%0], [%1], 16;" :: "r"(dst), "l"(src))
#define CP_COMMIT() asm volatile("cp.async.commit_group;" ::: "memory")
#define CP_WAIT(n)  asm volatile("cp.async.wait_group %0;" :: "n"(n) : "memory")

__device__ __forceinline__ void mma16(float c[4], const uint32_t a[4],
                                      const uint32_t b[2]) {
    asm volatile(
        "mma.sync.aligned.m16n8k16.row.col.f32.f16.f16.f32 "
        "{%0,%1,%2,%3}, {%4,%5,%6,%7}, {%8,%9}, {%0,%1,%2,%3};"
        : "+f"(c[0]), "+f"(c[1]), "+f"(c[2]), "+f"(c[3])
        : "r"(a[0]), "r"(a[1]), "r"(a[2]), "r"(a[3]), "r"(b[0]), "r"(b[1]));
}

// ===========================================================================
// GEMM engine (proj: 128x128 tiles; final: 64x128 tiles for grid occupancy)
// ===========================================================================
#define BK    32
#define LDSW  40

#define MODE_PROJ   0
#define MODE_FINAL  3

template <int MODE>
__global__ void __launch_bounds__(256, 2)
gemm_mma(const float* __restrict__ pBias, float* __restrict__ pC) {
    constexpr int TM = (MODE == MODE_PROJ) ? 128 : 64;
    constexpr int TN = 128;
    constexpr int MI = TM / 32;            // m-tiles per warp (warp covers TM/2)
    constexpr int ABUF = TM * LDSW;        // halves
    constexpr int BBUF = TN * LDSW;

    extern __shared__ __half smem[];
    const uint32_t sb0 = smem_u32(smem);
    const uint32_t aB[2] = { sb0, sb0 + ABUF * 2 };
    const uint32_t bB[2] = { sb0 + 2 * ABUF * 2, sb0 + 2 * ABUF * 2 + BBUF * 2 };

    const int tid  = threadIdx.x;
    const int lane = tid & 31, wid = tid >> 5;
    const int g    = lane >> 2, tig = lane & 3;
    const int wm   = (wid & 1) * (TM / 2);
    const int wn   = (wid >> 1) * 32;
    const int m0   = blockIdx.y * TM, n0 = blockIdx.x * TN;
    const int z    = blockIdx.z;

    const __half *Ah, *Bh;
    int lda, ldb, nch;
    if (MODE == MODE_PROJ) {
        Ah = g_Xh; lda = KD;
        Bh = g_Wth + (size_t)z * NPROJ * KD; ldb = KD; nch = KD / BK;
    } else {
        Ah = g_Oh;   lda = NPROJ;
        Bh = g_Wuth; ldb = NPROJ;        nch = NPROJ / BK;
    }

    auto issue_chunk = [&](int c, int st) {
        const int k0 = c * BK;
        #pragma unroll
        for (int u = tid; u < TM * 4; u += 256) {
            const int r = u >> 2, cc = (u & 3) * 8;
            CP_ASYNC16(aB[st] + (uint32_t)((r * LDSW + cc) * 2),
                       &Ah[(size_t)(m0 + r) * lda + k0 + cc]);
        }
        #pragma unroll
        for (int u = tid; u < TN * 4; u += 256) {
            const int r = u >> 2, cc = (u & 3) * 8;
            CP_ASYNC16(bB[st] + (uint32_t)((r * LDSW + cc) * 2),
                       &Bh[(size_t)(n0 + r) * ldb + k0 + cc]);
        }
    };

    float acc[MI][4][4];
    #pragma unroll
    for (int mi = 0; mi < MI; mi++)
        #pragma unroll
        for (int ni = 0; ni < 4; ni++)
            #pragma unroll
            for (int r = 0; r < 4; r++) acc[mi][ni][r] = 0.f;

    const int lm_row = lane & 15, lm_k8 = (lane >> 4) * 8;

    issue_chunk(0, 0); CP_COMMIT();
    issue_chunk(1, 1); CP_COMMIT();

    for (int c = 0; c < nch; c++) {
        const int st = c & 1;
        if (c + 1 < nch) CP_WAIT(1); else CP_WAIT(0);
        __syncthreads();
        #pragma unroll
        for (int ks = 0; ks < 2; ks++) {
            const int k = ks * 16;
            uint32_t af[MI][4], bf[4][2];
            #pragma unroll
            for (int mi = 0; mi < MI; mi++) {
                uint32_t ad = aB[st] +
                    (uint32_t)(((wm + mi * 16 + lm_row) * LDSW + k + lm_k8) * 2);
                LDSM_X4(af[mi][0], af[mi][1], af[mi][2], af[mi][3], ad);
            }
            #pragma unroll
            for (int nj = 0; nj < 2; nj++) {
                uint32_t bd = bB[st] +
                    (uint32_t)(((wn + nj * 16 + lm_row) * LDSW + k + lm_k8) * 2);
                LDSM_X4(bf[2 * nj][0], bf[2 * nj + 1][0],
                        bf[2 * nj][1], bf[2 * nj + 1][1], bd);
            }
            #pragma unroll
            for (int mi = 0; mi < MI; mi++)
                #pragma unroll
                for (int ni = 0; ni < 4; ni++)
                    mma16(acc[mi][ni], af[mi], bf[ni]);
        }
        __syncthreads();
        if (c + 2 < nch) { issue_chunk(c + 2, st); CP_COMMIT(); }
    }

    // ------------------- epilogue -------------------------------
    if (MODE == MODE_PROJ && z == 2) {
        // V: stage transposed tile in smem, then coalesced column writes.
        __half* epi = smem;
        #pragma unroll
        for (int mi = 0; mi < MI; mi++) {
            const int rl0 = wm + mi * 16 + g;
            #pragma unroll
            for (int ni = 0; ni < 4; ni++) {
                const int cl = wn + ni * 8 + tig * 2;
                const float* v = acc[mi][ni];
                epi[(cl)     * 136 + rl0]     = __float2half_rn(v[0]);
                epi[(cl + 1) * 136 + rl0]     = __float2half_rn(v[1]);
                epi[(cl)     * 136 + rl0 + 8] = __float2half_rn(v[2]);
                epi[(cl + 1) * 136 + rl0 + 8] = __float2half_rn(v[3]);
            }
        }
        __syncthreads();
        const int head = n0 >> 8;
        const int colh0 = n0 & 255;
        const int b_ = m0 >> 11, t0 = m0 & 2047;
        const int col = tid >> 1, sub = tid & 1;
        __half* dst = g_Vth + (((size_t)(b_ * H + head)) * KD + colh0 + col) * T + t0;
        #pragma unroll
        for (int j = 0; j < 8; j++) {
            const int row = sub * 8 + j * 16;
            *(uint4*)&dst[row] = *(const uint4*)&epi[col * 136 + row];
        }
        return;
    }

    #pragma unroll
    for (int mi = 0; mi < MI; mi++) {
        const int r0 = m0 + wm + mi * 16 + g;
        const int r1 = r0 + 8;
        #pragma unroll
        for (int ni = 0; ni < 4; ni++) {
            const int cc = n0 + wn + ni * 8 + tig * 2;
            const float* v = acc[mi][ni];
            if (MODE == MODE_PROJ) {
                const int head = n0 >> 8;
                const int colh = (n0 & 255) + wn + ni * 8 + tig * 2;
                const int b0_ = r0 >> 11, t0_ = r0 & 2047;
                const int b1_ = r1 >> 11, t1_ = r1 & 2047;
                const float scale = (z == 0) ? 0.25f * LOG2E : 0.25f;
                __half* Cb = (z == 0) ? g_Qh : g_Kh;
                *(uint32_t*)&Cb[(((size_t)(b0_ * H + head)) * T + t0_) * KD + colh] =
                    packh2(v[0] * scale, v[1] * scale);
                *(uint32_t*)&Cb[(((size_t)(b1_ * H + head)) * T + t1_) * KD + colh] =
                    packh2(v[2] * scale, v[3] * scale);
            } else {
                const float b0v = pBias[cc], b1v = pBias[cc + 1];
                *(float2*)&pC[(size_t)r0 * KD + cc] = make_float2(v[0] + b0v, v[1] + b1v);
                *(float2*)&pC[(size_t)r1 * KD + cc] = make_float2(v[2] + b0v, v[3] + b1v);
            }
        }
    }
}

#define SM_GEMM_PROJ  (2 * (128 * LDSW + 128 * LDSW) * 2)   // 40960
#define SM_GEMM_FINAL (2 * (64 * LDSW + 128 * LDSW) * 2)    // 30720

// ===========================================================================
// Fused flash attention — S-phase fragment double-buffering
// ===========================================================================
#define FK   64                        // keys per chunk
#define NCH  (T / FK)                  // 32 chunks
#define LQ   264
#define LK   264
#define LV   72
#define SMQ_BYTES (128 * LQ * 2)
#define SMK_BYTES (FK * LK * 2)
#define SMV_BYTES (256 * LV * 2)
#define SM_FLASH (SMQ_BYTES + 2 * SMK_BYTES + 2 * SMV_BYTES)   // 208896

__global__ void __launch_bounds__(256, 1)
flash_kernel() {
    extern __shared__ __half sm[];
    const uint32_t sb = smem_u32(sm);
    const uint32_t sQ = sb;
    const uint32_t sK[2] = { sb + SMQ_BYTES, sb + SMQ_BYTES + SMK_BYTES };
    const uint32_t sV[2] = { sb + SMQ_BYTES + 2 * SMK_BYTES,
                             sb + SMQ_BYTES + 2 * SMK_BYTES + SMV_BYTES };

    const int tid = threadIdx.x;
    const int lane = tid & 31, wid = tid >> 5;
    const int g = lane >> 2, tig = lane & 3;
    const int lm_row = lane & 15, lm_k8 = (lane >> 4) * 8;

    const int q0 = blockIdx.x * 128;
    const int bh = blockIdx.y;
    const __half* __restrict__ Qg = g_Qh + ((size_t)bh * T + q0) * KD;
    const __half* __restrict__ Kg = g_Kh + (size_t)bh * T * KD;
    const __half* __restrict__ Vg = g_Vth + (size_t)bh * KD * T;

    {
        #pragma unroll
        for (int i = 0; i < 16; i++) {
            int idx = tid + i * 256;
            int r = idx >> 5, c = idx & 31;
            CP_ASYNC16(sQ + (uint32_t)((r * LQ + c * 8) * 2), Qg + r * KD + c * 8);
        }
    }
    auto issue_kv = [&](int ch, int buf) {
        const int s0 = ch * FK;
        #pragma unroll
        for (int i = 0; i < 8; i++) {
            int idx = tid + i * 256;
            int r = idx >> 5, c = idx & 31;
            CP_ASYNC16(sK[buf] + (uint32_t)((r * LK + c * 8) * 2),
                       Kg + (size_t)(s0 + r) * KD + c * 8);
        }
        #pragma unroll
        for (int i = 0; i < 8; i++) {
            int idx = tid + i * 256;
            int r = idx >> 3, c = idx & 7;
            CP_ASYNC16(sV[buf] + (uint32_t)((r * LV + c * 8) * 2),
                       Vg + (size_t)r * T + s0 + c * 8);
        }
    };

    issue_kv(0, 0);
    CP_COMMIT();
    issue_kv(1, 1);
    CP_COMMIT();

    float oacc[32][4];
    #pragma unroll
    for (int n = 0; n < 32; n++)
        #pragma unroll
        for (int r = 0; r < 4; r++) oacc[n][r] = 0.f;
    float m0 = -INFINITY, m1 = -INFINITY;
    float l0 = 0.f, l1 = 0.f;

    const uint32_t qrow_base = sQ + (uint32_t)(((wid * 16 + lm_row) * LQ + lm_k8) * 2);

    for (int ch = 0; ch < NCH; ch++) {
        if (ch < NCH - 1) CP_WAIT(1); else CP_WAIT(0);
        __syncthreads();
        const int buf = ch & 1;
        const uint32_t kbase = sK[buf] + (uint32_t)((lm_row * LK + lm_k8) * 2);

        // ---- S = Q K^T, fragment double-buffered over ks ----
        float sacc[8][4];
        #pragma unroll
        for (int n = 0; n < 8; n++)
            #pragma unroll
            for (int r = 0; r < 4; r++) sacc[n][r] = 0.f;

        uint32_t af2[2][4], bf2[2][8][2];
        // preload ks = 0
        LDSM_X4(af2[0][0], af2[0][1], af2[0][2], af2[0][3], qrow_base);
        #pragma unroll
        for (int nj = 0; nj < 4; nj++) {
            LDSM_X4(bf2[0][2 * nj][0], bf2[0][2 * nj + 1][0],
                    bf2[0][2 * nj][1], bf2[0][2 * nj + 1][1],
                    kbase + (uint32_t)(nj * 16 * LK * 2));
        }
        #pragma unroll
        for (int ks = 0; ks < 16; ks++) {
            const int cur = ks & 1, nxt = cur ^ 1;
            if (ks < 15) {
                const uint32_t ko = (uint32_t)((ks + 1) * 32);
                LDSM_X4(af2[nxt][0], af2[nxt][1], af2[nxt][2], af2[nxt][3],
                        qrow_base + ko);
                #pragma unroll
                for (int nj = 0; nj < 4; nj++) {
                    LDSM_X4(bf2[nxt][2 * nj][0], bf2[nxt][2 * nj + 1][0],
                            bf2[nxt][2 * nj][1], bf2[nxt][2 * nj + 1][1],
                            kbase + (uint32_t)(nj * 16 * LK * 2) + ko);
                }
            }
            #pragma unroll
            for (int nt = 0; nt < 8; nt++) mma16(sacc[nt], af2[cur], bf2[cur][nt]);
        }

        // ---- max reduction + rescale ----
        float cm0 = -INFINITY, cm1 = -INFINITY;
        #pragma unroll
        for (int nt = 0; nt < 8; nt++) {
            cm0 = fmaxf(cm0, fmaxf(sacc[nt][0], sacc[nt][1]));
            cm1 = fmaxf(cm1, fmaxf(sacc[nt][2], sacc[nt][3]));
        }
        cm0 = fmaxf(cm0, __shfl_xor_sync(0xffffffffu, cm0, 1));
        cm0 = fmaxf(cm0, __shfl_xor_sync(0xffffffffu, cm0, 2));
        cm1 = fmaxf(cm1, __shfl_xor_sync(0xffffffffu, cm1, 1));
        cm1 = fmaxf(cm1, __shfl_xor_sync(0xffffffffu, cm1, 2));

        const float mn0 = fmaxf(m0, cm0), mn1 = fmaxf(m1, cm1);
        const float al0 = exp2f(m0 - mn0), al1 = exp2f(m1 - mn1);
        m0 = mn0; m1 = mn1;

        #pragma unroll
        for (int n = 0; n < 32; n++) {
            oacc[n][0] *= al0; oacc[n][1] *= al0;
            oacc[n][2] *= al1; oacc[n][3] *= al1;
        }

        // ---- interleaved: exp/pack k-step ks2, then its PV MMAs ----
        float rs0 = 0.f, rs1 = 0.f;
        #pragma unroll
        for (int ks2 = 0; ks2 < 4; ks2++) {
            const int e0 = 2 * ks2, e1 = 2 * ks2 + 1;
            sacc[e0][0] = exp2f(sacc[e0][0] - mn0);
            sacc[e0][1] = exp2f(sacc[e0][1] - mn0);
            sacc[e0][2] = exp2f(sacc[e0][2] - mn1);
            sacc[e0][3] = exp2f(sacc[e0][3] - mn1);
            sacc[e1][0] = exp2f(sacc[e1][0] - mn0);
            sacc[e1][1] = exp2f(sacc[e1][1] - mn0);
            sacc[e1][2] = exp2f(sacc[e1][2] - mn1);
            sacc[e1][3] = exp2f(sacc[e1][3] - mn1);
            rs0 += sacc[e0][0] + sacc[e0][1] + sacc[e1][0] + sacc[e1][1];
            rs1 += sacc[e0][2] + sacc[e0][3] + sacc[e1][2] + sacc[e1][3];

            uint32_t pa[4];
            pa[0] = packh2(sacc[e0][0], sacc[e0][1]);
            pa[1] = packh2(sacc[e0][2], sacc[e0][3]);
            pa[2] = packh2(sacc[e1][0], sacc[e1][1]);
            pa[3] = packh2(sacc[e1][2], sacc[e1][3]);

            #pragma unroll
            for (int hv = 0; hv < 2; hv++) {
                uint32_t bv[16][2];
                #pragma unroll
                for (int nj = 0; nj < 8; nj++) {
                    uint32_t bd = sV[buf] +
                        (uint32_t)((((hv * 8 + nj) * 16 + lm_row) * LV +
                                    ks2 * 16 + lm_k8) * 2);
                    LDSM_X4(bv[2 * nj][0], bv[2 * nj + 1][0],
                            bv[2 * nj][1], bv[2 * nj + 1][1], bd);
                }
                #pragma unroll
                for (int nt = 0; nt < 16; nt++)
                    mma16(oacc[hv * 16 + nt], pa, bv[nt]);
            }
        }

        rs0 += __shfl_xor_sync(0xffffffffu, rs0, 1);
        rs0 += __shfl_xor_sync(0xffffffffu, rs0, 2);
        rs1 += __shfl_xor_sync(0xffffffffu, rs1, 1);
        rs1 += __shfl_xor_sync(0xffffffffu, rs1, 2);
        l0 = l0 * al0 + rs0;
        l1 = l1 * al1 + rs1;

        __syncthreads();
        if (ch + 2 < NCH) { issue_kv(ch + 2, buf); CP_COMMIT(); }
    }

    const float inv0 = 1.0f / l0, inv1 = 1.0f / l1;
    const int r0 = q0 + wid * 16 + g, r1 = r0 + 8;
    const int b_ = bh >> 3, head = bh & 7;
    __half* o0 = g_Oh + ((size_t)(b_ * T + r0)) * NPROJ + head * KD;
    __half* o1 = g_Oh + ((size_t)(b_ * T + r1)) * NPROJ + head * KD;
    #pragma unroll
    for (int nt = 0; nt < 32; nt++) {
        const int col = nt * 8 + tig * 2;
        *(uint32_t*)&o0[col] = packh2(oacc[nt][0] * inv0, oacc[nt][1] * inv0);
        *(uint32_t*)&o1[col] = packh2(oacc[nt][2] * inv1, oacc[nt][3] * inv1);
    }
}

// ---------------------------------------------------------------------------
// Merged prep kernel: grid (512, 5); y = task
//   0: convert x -> fp16; 1-3: transpose Wq/Wk/Wv; 4: transpose Wu
// ---------------------------------------------------------------------------
__global__ void prep_kernel(const float* __restrict__ x,
                            const float* __restrict__ Wq,
                            const float* __restrict__ Wk,
                            const float* __restrict__ Wv,
                            const float* __restrict__ Wu) {
    const int task = blockIdx.y;
    const int tid = threadIdx.x;
    if (task == 0) {
        const int base = (blockIdx.x * 256 + tid) * 8;
        float4 a = *(const float4*)&x[base];
        float4 b = *(const float4*)&x[base + 4];
        *(uint2*)&g_Xh[base]     = make_uint2(packh2(a.x, a.y), packh2(a.z, a.w));
        *(uint2*)&g_Xh[base + 4] = make_uint2(packh2(b.x, b.y), packh2(b.z, b.w));
        return;
    }
    __shared__ float t[32][33];
    const int xx = tid & 31, yy = tid >> 5;
    if (task <= 3) {
        const float* in = (task == 1) ? Wq : (task == 2) ? Wk : Wv;
        __half* out = g_Wth + (size_t)(task - 1) * NPROJ * KD;
        const int bx = blockIdx.x & 63, by = blockIdx.x >> 6;   // grid (64, 8)
        const int c0 = bx * 32, r0 = by * 32;
        #pragma unroll
        for (int i = 0; i < 32; i += 8)
            t[yy + i][xx] = in[(size_t)(r0 + yy + i) * NPROJ + c0 + xx];
        __syncthreads();
        #pragma unroll
        for (int i = 0; i < 32; i += 8)
            out[(size_t)(c0 + yy + i) * KD + r0 + xx] = __float2half_rn(t[xx][yy + i]);
    } else {
        const int bx = blockIdx.x & 7, by = blockIdx.x >> 3;    // grid (8, 64)
        const int c0 = bx * 32, r0 = by * 32;
        #pragma unroll
        for (int i = 0; i < 32; i += 8)
            t[yy + i][xx] = Wu[(size_t)(r0 + yy + i) * KD + c0 + xx];
        __syncthreads();
        #pragma unroll
        for (int i = 0; i < 32; i += 8)
            g_Wuth[(size_t)(c0 + yy + i) * NPROJ + r0 + xx] = __float2half_rn(t[xx][yy + i]);
    }
}

// ---------------------------------------------------------------------------
extern "C" void kernel_launch(void* const* d_in, const int* in_sizes, int n_in,
                              void* d_out, int out_size) {
    const float* x  = (const float*)d_in[0];
    const float* Wq = (const float*)d_in[1];
    const float* Wk = (const float*)d_in[2];
    const float* Wv = (const float*)d_in[3];
    const float* Wu = (const float*)d_in[4];
    const float* bu = (const float*)d_in[5];
    float* out = (float*)d_out;

    cudaFuncSetAttribute(flash_kernel,
                         cudaFuncAttributeMaxDynamicSharedMemorySize, SM_FLASH);

    // 0) one-shot prep (x->fp16, weight transposes)
    prep_kernel<<<dim3(512, 5), 256>>>(x, Wq, Wk, Wv, Wu);

    // 1) projections (z = {q,k,v}); V transposed via smem; Q has log2e folded
    gemm_mma<MODE_PROJ><<<dim3(NPROJ / 128, ROWS / 128, 3), 256, SM_GEMM_PROJ>>>(
        nullptr, nullptr);

    // 2) fused attention -> g_Oh
    flash_kernel<<<dim3(T / 128, BH), 256, SM_FLASH>>>();

    // 3) out = O @ Wu + bu (fp32), 64x128 tiles -> 128 CTAs
    gemm_mma<MODE_FINAL><<<dim3(KD / 128, ROWS / 64, 1), 256, SM_GEMM_FINAL>>>(
        bu, out);
}

// round 11
// speedup vs baseline: 12.2810x; 1.0325x over previous
#include <cuda_runtime.h>
#include <cuda_fp16.h>
#include <math.h>
#include <stdint.h>

// Problem shape (fixed)
#define B   2
#define T   2048
#define KD  256
#define H   8
#define BH  (B*H)        // 16
#define NPROJ (KD*H)     // 2048
#define ROWS (B*T)       // 4096

#define LOG2E 1.4426950408889634f
#define KSPLIT 4

// ---------------------------------------------------------------------------
// Scratch (device globals — allocation-free per harness rules)
// ---------------------------------------------------------------------------
__device__ __half g_Xh [ROWS * KD];            // x in fp16
__device__ __half g_Qh [BH * T * KD];          // [bh][t][kd] * 0.25*log2e
__device__ __half g_Kh [BH * T * KD];          // [bh][t][kd] * 0.25
__device__ __half g_Vth[BH * KD * T];          // [bh][kd][t]
__device__ __half g_Oh [ROWS * NPROJ];         // [b*t][h*kd]
__device__ __half g_Wth [3 * NPROJ * KD];      // Wq^T,Wk^T,Wv^T fp16 [n][k]
__device__ __half g_Wuth[KD * NPROJ];          // Wu^T fp16 [256][2048]

// ---------------------------------------------------------------------------
// Common PTX helpers
// ---------------------------------------------------------------------------
__device__ __forceinline__ uint32_t smem_u32(const void* p) {
    uint32_t a;
    asm("{ .reg .u64 t; cvta.to.shared.u64 t, %1; cvt.u32.u64 %0, t; }"
        : "=r"(a) : "l"(p));
    return a;
}
__device__ __forceinline__ uint32_t packh2(float x, float y) {
    __half2 h = __floats2half2_rn(x, y);
    return *(uint32_t*)&h;
}
#define LDSM_X4(r0, r1, r2, r3, addr) \
    asm volatile("ldmatrix.sync.aligned.m8n8.x4.shared.b16 {%0,%1,%2,%3}, [%4];" \
                 : "=r"(r0), "=r"(r1), "=r"(r2), "=r"(r3) : "r"(addr))
#define CP_ASYNC16(dst, src) \
    asm volatile("cp.async.cg.shared.global [%0], [%1], 16;" :: "r"(dst), "l"(src))
#define CP_COMMIT() asm volatile("cp.async.commit_group;" ::: "memory")
#define CP_WAIT(n)  asm volatile("cp.async.wait_group %0;" :: "n"(n) : "memory")

__device__ __forceinline__ void mma16(float c[4], const uint32_t a[4],
                                      const uint32_t b[2]) {
    asm volatile(
        "mma.sync.aligned.m16n8k16.row.col.f32.f16.f16.f32 "
        "{%0,%1,%2,%3}, {%4,%5,%6,%7}, {%8,%9}, {%0,%1,%2,%3};"
        : "+f"(c[0]), "+f"(c[1]), "+f"(c[2]), "+f"(c[3])
        : "r"(a[0]), "r"(a[1]), "r"(a[2]), "r"(a[3]), "r"(b[0]), "r"(b[1]));
}

// ===========================================================================
// GEMM engine (proj: 128x128 tiles; final: 64x128 tiles, split-K=4)
// ===========================================================================
#define BK    32
#define LDSW  40

#define MODE_PROJ   0
#define MODE_FINAL  3

template <int MODE>
__global__ void __launch_bounds__(256, 2)
gemm_mma(const float* __restrict__ pBias, float* __restrict__ pC) {
    constexpr int TM = (MODE == MODE_PROJ) ? 128 : 64;
    constexpr int TN = 128;
    constexpr int MI = TM / 32;            // m-tiles per warp (warp covers TM/2)
    constexpr int ABUF = TM * LDSW;        // halves
    constexpr int BBUF = TN * LDSW;

    extern __shared__ __half smem[];
    const uint32_t sb0 = smem_u32(smem);
    const uint32_t aB[2] = { sb0, sb0 + ABUF * 2 };
    const uint32_t bB[2] = { sb0 + 2 * ABUF * 2, sb0 + 2 * ABUF * 2 + BBUF * 2 };

    const int tid  = threadIdx.x;
    const int lane = tid & 31, wid = tid >> 5;
    const int g    = lane >> 2, tig = lane & 3;
    const int wm   = (wid & 1) * (TM / 2);
    const int wn   = (wid >> 1) * 32;
    const int m0   = blockIdx.y * TM, n0 = blockIdx.x * TN;
    const int z    = blockIdx.z;

    const __half *Ah, *Bh;
    int lda, ldb, nch, kbase;
    if (MODE == MODE_PROJ) {
        Ah = g_Xh; lda = KD;
        Bh = g_Wth + (size_t)z * NPROJ * KD; ldb = KD;
        nch = KD / BK; kbase = 0;
    } else {
        Ah = g_Oh;   lda = NPROJ;
        Bh = g_Wuth; ldb = NPROJ;
        nch = NPROJ / BK / KSPLIT;               // 16 chunks per split
        kbase = z * (NPROJ / KSPLIT);            // 512 * z
    }

    auto issue_chunk = [&](int c, int st) {
        const int k0 = kbase + c * BK;
        #pragma unroll
        for (int u = tid; u < TM * 4; u += 256) {
            const int r = u >> 2, cc = (u & 3) * 8;
            CP_ASYNC16(aB[st] + (uint32_t)((r * LDSW + cc) * 2),
                       &Ah[(size_t)(m0 + r) * lda + k0 + cc]);
        }
        #pragma unroll
        for (int u = tid; u < TN * 4; u += 256) {
            const int r = u >> 2, cc = (u & 3) * 8;
            CP_ASYNC16(bB[st] + (uint32_t)((r * LDSW + cc) * 2),
                       &Bh[(size_t)(n0 + r) * ldb + k0 + cc]);
        }
    };

    float acc[MI][4][4];
    #pragma unroll
    for (int mi = 0; mi < MI; mi++)
        #pragma unroll
        for (int ni = 0; ni < 4; ni++)
            #pragma unroll
            for (int r = 0; r < 4; r++) acc[mi][ni][r] = 0.f;

    const int lm_row = lane & 15, lm_k8 = (lane >> 4) * 8;

    issue_chunk(0, 0); CP_COMMIT();
    issue_chunk(1, 1); CP_COMMIT();

    for (int c = 0; c < nch; c++) {
        const int st = c & 1;
        if (c + 1 < nch) CP_WAIT(1); else CP_WAIT(0);
        __syncthreads();
        #pragma unroll
        for (int ks = 0; ks < 2; ks++) {
            const int k = ks * 16;
            uint32_t af[MI][4], bf[4][2];
            #pragma unroll
            for (int mi = 0; mi < MI; mi++) {
                uint32_t ad = aB[st] +
                    (uint32_t)(((wm + mi * 16 + lm_row) * LDSW + k + lm_k8) * 2);
                LDSM_X4(af[mi][0], af[mi][1], af[mi][2], af[mi][3], ad);
            }
            #pragma unroll
            for (int nj = 0; nj < 2; nj++) {
                uint32_t bd = bB[st] +
                    (uint32_t)(((wn + nj * 16 + lm_row) * LDSW + k + lm_k8) * 2);
                LDSM_X4(bf[2 * nj][0], bf[2 * nj + 1][0],
                        bf[2 * nj][1], bf[2 * nj + 1][1], bd);
            }
            #pragma unroll
            for (int mi = 0; mi < MI; mi++)
                #pragma unroll
                for (int ni = 0; ni < 4; ni++)
                    mma16(acc[mi][ni], af[mi], bf[ni]);
        }
        __syncthreads();
        if (c + 2 < nch) { issue_chunk(c + 2, st); CP_COMMIT(); }
    }

    // ------------------- epilogue -------------------------------
    if (MODE == MODE_PROJ && z == 2) {
        // V: stage transposed tile in smem, then coalesced column writes.
        __half* epi = smem;
        #pragma unroll
        for (int mi = 0; mi < MI; mi++) {
            const int rl0 = wm + mi * 16 + g;
            #pragma unroll
            for (int ni = 0; ni < 4; ni++) {
                const int cl = wn + ni * 8 + tig * 2;
                const float* v = acc[mi][ni];
                epi[(cl)     * 136 + rl0]     = __float2half_rn(v[0]);
                epi[(cl + 1) * 136 + rl0]     = __float2half_rn(v[1]);
                epi[(cl)     * 136 + rl0 + 8] = __float2half_rn(v[2]);
                epi[(cl + 1) * 136 + rl0 + 8] = __float2half_rn(v[3]);
            }
        }
        __syncthreads();
        const int head = n0 >> 8;
        const int colh0 = n0 & 255;
        const int b_ = m0 >> 11, t0 = m0 & 2047;
        const int col = tid >> 1, sub = tid & 1;
        __half* dst = g_Vth + (((size_t)(b_ * H + head)) * KD + colh0 + col) * T + t0;
        #pragma unroll
        for (int j = 0; j < 8; j++) {
            const int row = sub * 8 + j * 16;
            *(uint4*)&dst[row] = *(const uint4*)&epi[col * 136 + row];
        }
        return;
    }

    #pragma unroll
    for (int mi = 0; mi < MI; mi++) {
        const int r0 = m0 + wm + mi * 16 + g;
        const int r1 = r0 + 8;
        #pragma unroll
        for (int ni = 0; ni < 4; ni++) {
            const int cc = n0 + wn + ni * 8 + tig * 2;
            const float* v = acc[mi][ni];
            if (MODE == MODE_PROJ) {
                const int head = n0 >> 8;
                const int colh = (n0 & 255) + wn + ni * 8 + tig * 2;
                const int b0_ = r0 >> 11, t0_ = r0 & 2047;
                const int b1_ = r1 >> 11, t1_ = r1 & 2047;
                const float scale = (z == 0) ? 0.25f * LOG2E : 0.25f;
                __half* Cb = (z == 0) ? g_Qh : g_Kh;
                *(uint32_t*)&Cb[(((size_t)(b0_ * H + head)) * T + t0_) * KD + colh] =
                    packh2(v[0] * scale, v[1] * scale);
                *(uint32_t*)&Cb[(((size_t)(b1_ * H + head)) * T + t1_) * KD + colh] =
                    packh2(v[2] * scale, v[3] * scale);
            } else {
                // split-K: accumulate into bias-initialized output
                atomicAdd(&pC[(size_t)r0 * KD + cc],     v[0]);
                atomicAdd(&pC[(size_t)r0 * KD + cc + 1], v[1]);
                atomicAdd(&pC[(size_t)r1 * KD + cc],     v[2]);
                atomicAdd(&pC[(size_t)r1 * KD + cc + 1], v[3]);
            }
        }
    }
}

#define SM_GEMM_PROJ  (2 * (128 * LDSW + 128 * LDSW) * 2)   // 40960
#define SM_GEMM_FINAL (2 * (64 * LDSW + 128 * LDSW) * 2)    // 30720

// ===========================================================================
// Fused flash attention — S-phase fragment double-buffering
// ===========================================================================
#define FK   64                        // keys per chunk
#define NCH  (T / FK)                  // 32 chunks
#define LQ   264
#define LK   264
#define LV   72
#define SMQ_BYTES (128 * LQ * 2)
#define SMK_BYTES (FK * LK * 2)
#define SMV_BYTES (256 * LV * 2)
#define SM_FLASH (SMQ_BYTES + 2 * SMK_BYTES + 2 * SMV_BYTES)   // 208896

__global__ void __launch_bounds__(256, 1)
flash_kernel() {
    extern __shared__ __half sm[];
    const uint32_t sb = smem_u32(sm);
    const uint32_t sQ = sb;
    const uint32_t sK[2] = { sb + SMQ_BYTES, sb + SMQ_BYTES + SMK_BYTES };
    const uint32_t sV[2] = { sb + SMQ_BYTES + 2 * SMK_BYTES,
                             sb + SMQ_BYTES + 2 * SMK_BYTES + SMV_BYTES };

    const int tid = threadIdx.x;
    const int lane = tid & 31, wid = tid >> 5;
    const int g = lane >> 2, tig = lane & 3;
    const int lm_row = lane & 15, lm_k8 = (lane >> 4) * 8;

    const int q0 = blockIdx.x * 128;
    const int bh = blockIdx.y;
    const __half* __restrict__ Qg = g_Qh + ((size_t)bh * T + q0) * KD;
    const __half* __restrict__ Kg = g_Kh + (size_t)bh * T * KD;
    const __half* __restrict__ Vg = g_Vth + (size_t)bh * KD * T;

    {
        #pragma unroll
        for (int i = 0; i < 16; i++) {
            int idx = tid + i * 256;
            int r = idx >> 5, c = idx & 31;
            CP_ASYNC16(sQ + (uint32_t)((r * LQ + c * 8) * 2), Qg + r * KD + c * 8);
        }
    }
    auto issue_kv = [&](int ch, int buf) {
        const int s0 = ch * FK;
        #pragma unroll
        for (int i = 0; i < 8; i++) {
            int idx = tid + i * 256;
            int r = idx >> 5, c = idx & 31;
            CP_ASYNC16(sK[buf] + (uint32_t)((r * LK + c * 8) * 2),
                       Kg + (size_t)(s0 + r) * KD + c * 8);
        }
        #pragma unroll
        for (int i = 0; i < 8; i++) {
            int idx = tid + i * 256;
            int r = idx >> 3, c = idx & 7;
            CP_ASYNC16(sV[buf] + (uint32_t)((r * LV + c * 8) * 2),
                       Vg + (size_t)r * T + s0 + c * 8);
        }
    };

    issue_kv(0, 0);
    CP_COMMIT();
    issue_kv(1, 1);
    CP_COMMIT();

    float oacc[32][4];
    #pragma unroll
    for (int n = 0; n < 32; n++)
        #pragma unroll
        for (int r = 0; r < 4; r++) oacc[n][r] = 0.f;
    float m0 = -INFINITY, m1 = -INFINITY;
    float l0 = 0.f, l1 = 0.f;

    const uint32_t qrow_base = sQ + (uint32_t)(((wid * 16 + lm_row) * LQ + lm_k8) * 2);

    for (int ch = 0; ch < NCH; ch++) {
        if (ch < NCH - 1) CP_WAIT(1); else CP_WAIT(0);
        __syncthreads();
        const int buf = ch & 1;
        const uint32_t kbase = sK[buf] + (uint32_t)((lm_row * LK + lm_k8) * 2);

        // ---- S = Q K^T, fragment double-buffered over ks ----
        float sacc[8][4];
        #pragma unroll
        for (int n = 0; n < 8; n++)
            #pragma unroll
            for (int r = 0; r < 4; r++) sacc[n][r] = 0.f;

        uint32_t af2[2][4], bf2[2][8][2];
        LDSM_X4(af2[0][0], af2[0][1], af2[0][2], af2[0][3], qrow_base);
        #pragma unroll
        for (int nj = 0; nj < 4; nj++) {
            LDSM_X4(bf2[0][2 * nj][0], bf2[0][2 * nj + 1][0],
                    bf2[0][2 * nj][1], bf2[0][2 * nj + 1][1],
                    kbase + (uint32_t)(nj * 16 * LK * 2));
        }
        #pragma unroll
        for (int ks = 0; ks < 16; ks++) {
            const int cur = ks & 1, nxt = cur ^ 1;
            if (ks < 15) {
                const uint32_t ko = (uint32_t)((ks + 1) * 32);
                LDSM_X4(af2[nxt][0], af2[nxt][1], af2[nxt][2], af2[nxt][3],
                        qrow_base + ko);
                #pragma unroll
                for (int nj = 0; nj < 4; nj++) {
                    LDSM_X4(bf2[nxt][2 * nj][0], bf2[nxt][2 * nj + 1][0],
                            bf2[nxt][2 * nj][1], bf2[nxt][2 * nj + 1][1],
                            kbase + (uint32_t)(nj * 16 * LK * 2) + ko);
                }
            }
            #pragma unroll
            for (int nt = 0; nt < 8; nt++) mma16(sacc[nt], af2[cur], bf2[cur][nt]);
        }

        // ---- max reduction + rescale ----
        float cm0 = -INFINITY, cm1 = -INFINITY;
        #pragma unroll
        for (int nt = 0; nt < 8; nt++) {
            cm0 = fmaxf(cm0, fmaxf(sacc[nt][0], sacc[nt][1]));
            cm1 = fmaxf(cm1, fmaxf(sacc[nt][2], sacc[nt][3]));
        }
        cm0 = fmaxf(cm0, __shfl_xor_sync(0xffffffffu, cm0, 1));
        cm0 = fmaxf(cm0, __shfl_xor_sync(0xffffffffu, cm0, 2));
        cm1 = fmaxf(cm1, __shfl_xor_sync(0xffffffffu, cm1, 1));
        cm1 = fmaxf(cm1, __shfl_xor_sync(0xffffffffu, cm1, 2));

        const float mn0 = fmaxf(m0, cm0), mn1 = fmaxf(m1, cm1);
        const float al0 = exp2f(m0 - mn0), al1 = exp2f(m1 - mn1);
        m0 = mn0; m1 = mn1;

        #pragma unroll
        for (int n = 0; n < 32; n++) {
            oacc[n][0] *= al0; oacc[n][1] *= al0;
            oacc[n][2] *= al1; oacc[n][3] *= al1;
        }

        // ---- interleaved: exp/pack k-step ks2, then its PV MMAs ----
        float rs0 = 0.f, rs1 = 0.f;
        #pragma unroll
        for (int ks2 = 0; ks2 < 4; ks2++) {
            const int e0 = 2 * ks2, e1 = 2 * ks2 + 1;
            sacc[e0][0] = exp2f(sacc[e0][0] - mn0);
            sacc[e0][1] = exp2f(sacc[e0][1] - mn0);
            sacc[e0][2] = exp2f(sacc[e0][2] - mn1);
            sacc[e0][3] = exp2f(sacc[e0][3] - mn1);
            sacc[e1][0] = exp2f(sacc[e1][0] - mn0);
            sacc[e1][1] = exp2f(sacc[e1][1] - mn0);
            sacc[e1][2] = exp2f(sacc[e1][2] - mn1);
            sacc[e1][3] = exp2f(sacc[e1][3] - mn1);
            rs0 += sacc[e0][0] + sacc[e0][1] + sacc[e1][0] + sacc[e1][1];
            rs1 += sacc[e0][2] + sacc[e0][3] + sacc[e1][2] + sacc[e1][3];

            uint32_t pa[4];
            pa[0] = packh2(sacc[e0][0], sacc[e0][1]);
            pa[1] = packh2(sacc[e0][2], sacc[e0][3]);
            pa[2] = packh2(sacc[e1][0], sacc[e1][1]);
            pa[3] = packh2(sacc[e1][2], sacc[e1][3]);

            #pragma unroll
            for (int hv = 0; hv < 2; hv++) {
                uint32_t bv[16][2];
                #pragma unroll
                for (int nj = 0; nj < 8; nj++) {
                    uint32_t bd = sV[buf] +
                        (uint32_t)((((hv * 8 + nj) * 16 + lm_row) * LV +
                                    ks2 * 16 + lm_k8) * 2);
                    LDSM_X4(bv[2 * nj][0], bv[2 * nj + 1][0],
                            bv[2 * nj][1], bv[2 * nj + 1][1], bd);
                }
                #pragma unroll
                for (int nt = 0; nt < 16; nt++)
                    mma16(oacc[hv * 16 + nt], pa, bv[nt]);
            }
        }

        rs0 += __shfl_xor_sync(0xffffffffu, rs0, 1);
        rs0 += __shfl_xor_sync(0xffffffffu, rs0, 2);
        rs1 += __shfl_xor_sync(0xffffffffu, rs1, 1);
        rs1 += __shfl_xor_sync(0xffffffffu, rs1, 2);
        l0 = l0 * al0 + rs0;
        l1 = l1 * al1 + rs1;

        __syncthreads();
        if (ch + 2 < NCH) { issue_kv(ch + 2, buf); CP_COMMIT(); }
    }

    const float inv0 = 1.0f / l0, inv1 = 1.0f / l1;
    const int r0 = q0 + wid * 16 + g, r1 = r0 + 8;
    const int b_ = bh >> 3, head = bh & 7;
    __half* o0 = g_Oh + ((size_t)(b_ * T + r0)) * NPROJ + head * KD;
    __half* o1 = g_Oh + ((size_t)(b_ * T + r1)) * NPROJ + head * KD;
    #pragma unroll
    for (int nt = 0; nt < 32; nt++) {
        const int col = nt * 8 + tig * 2;
        *(uint32_t*)&o0[col] = packh2(oacc[nt][0] * inv0, oacc[nt][1] * inv0);
        *(uint32_t*)&o1[col] = packh2(oacc[nt][2] * inv1, oacc[nt][3] * inv1);
    }
}

// ---------------------------------------------------------------------------
// Merged prep kernel: grid (512, 6); y = task
//   0: convert x -> fp16; 1-3: transpose Wq/Wk/Wv; 4: transpose Wu
//   5: init out with bias (for split-K accumulation)
// ---------------------------------------------------------------------------
__global__ void prep_kernel(const float* __restrict__ x,
                            const float* __restrict__ Wq,
                            const float* __restrict__ Wk,
                            const float* __restrict__ Wv,
                            const float* __restrict__ Wu,
                            const float* __restrict__ bu,
                            float* __restrict__ out) {
    const int task = blockIdx.y;
    const int tid = threadIdx.x;
    if (task == 0) {
        const int base = (blockIdx.x * 256 + tid) * 8;
        float4 a = *(const float4*)&x[base];
        float4 b = *(const float4*)&x[base + 4];
        *(uint2*)&g_Xh[base]     = make_uint2(packh2(a.x, a.y), packh2(a.z, a.w));
        *(uint2*)&g_Xh[base + 4] = make_uint2(packh2(b.x, b.y), packh2(b.z, b.w));
        return;
    }
    if (task == 5) {
        const int base = (blockIdx.x * 256 + tid) * 8;   // col = base & 255
        const int c0 = base & 255;
        float4 b0 = *(const float4*)&bu[c0];
        float4 b1 = *(const float4*)&bu[c0 + 4];
        *(float4*)&out[base]     = b0;
        *(float4*)&out[base + 4] = b1;
        return;
    }
    __shared__ float t[32][33];
    const int xx = tid & 31, yy = tid >> 5;
    if (task <= 3) {
        const float* in = (task == 1) ? Wq : (task == 2) ? Wk : Wv;
        __half* outw = g_Wth + (size_t)(task - 1) * NPROJ * KD;
        const int bx = blockIdx.x & 63, by = blockIdx.x >> 6;   // grid (64, 8)
        const int c0 = bx * 32, r0 = by * 32;
        #pragma unroll
        for (int i = 0; i < 32; i += 8)
            t[yy + i][xx] = in[(size_t)(r0 + yy + i) * NPROJ + c0 + xx];
        __syncthreads();
        #pragma unroll
        for (int i = 0; i < 32; i += 8)
            outw[(size_t)(c0 + yy + i) * KD + r0 + xx] = __float2half_rn(t[xx][yy + i]);
    } else {
        const int bx = blockIdx.x & 7, by = blockIdx.x >> 3;    // grid (8, 64)
        const int c0 = bx * 32, r0 = by * 32;
        #pragma unroll
        for (int i = 0; i < 32; i += 8)
            t[yy + i][xx] = Wu[(size_t)(r0 + yy + i) * KD + c0 + xx];
        __syncthreads();
        #pragma unroll
        for (int i = 0; i < 32; i += 8)
            g_Wuth[(size_t)(c0 + yy + i) * NPROJ + r0 + xx] = __float2half_rn(t[xx][yy + i]);
    }
}

// ---------------------------------------------------------------------------
extern "C" void kernel_launch(void* const* d_in, const int* in_sizes, int n_in,
                              void* d_out, int out_size) {
    const float* x  = (const float*)d_in[0];
    const float* Wq = (const float*)d_in[1];
    const float* Wk = (const float*)d_in[2];
    const float* Wv = (const float*)d_in[3];
    const float* Wu = (const float*)d_in[4];
    const float* bu = (const float*)d_in[5];
    float* out = (float*)d_out;

    cudaFuncSetAttribute(flash_kernel,
                         cudaFuncAttributeMaxDynamicSharedMemorySize, SM_FLASH);

    // 0) one-shot prep (x->fp16, weight transposes, out := bias)
    prep_kernel<<<dim3(512, 6), 256>>>(x, Wq, Wk, Wv, Wu, bu, out);

    // 1) projections (z = {q,k,v}); V transposed via smem; Q has log2e folded
    gemm_mma<MODE_PROJ><<<dim3(NPROJ / 128, ROWS / 128, 3), 256, SM_GEMM_PROJ>>>(
        nullptr, nullptr);

    // 2) fused attention -> g_Oh
    flash_kernel<<<dim3(T / 128, BH), 256, SM_FLASH>>>();

    // 3) out += O @ Wu (split-K=4, atomic accumulate onto bias)
    gemm_mma<MODE_FINAL><<<dim3(KD / 128, ROWS / 64, KSPLIT), 256, SM_GEMM_FINAL>>>(
        nullptr, out);
}